// round 1
// baseline (speedup 1.0000x reference)
#include <cuda_runtime.h>

#define Bc 8
#define Sc 2048
#define Mc 512
#define Ec 1024
#define Hc 16
#define Dc 64

// ---------------- scratch (static device globals; no runtime allocation) ----
__device__ float g_Qp [(size_t)Bc*Sc*Ec];   // 64 MB  Q projection
__device__ float g_attn[(size_t)Bc*Sc*Ec];  // 64 MB  attention output
__device__ float g_proj[(size_t)Bc*Sc*Ec];  // 64 MB  out-proj result
__device__ float g_Kp [Mc*Ec];              // 2 MB
__device__ float g_Vp [Mc*Ec];              // 2 MB
__device__ float g_gmem[Mc*Ec];             // 2 MB   mem @ gate_w[:, :E]^T + gate_b
__device__ float g_wqpart[8*Bc*Ec];
__device__ float g_wq  [Bc*Ec];
__device__ float g_vw  [Bc*Ec];
__device__ float g_upd [Bc*Ec];
__device__ float g_gupd[Bc*Ec];

// ---------------- SGEMM (NT): C[i,j] = sum_k A[i,k]*W[j,k] + bias[j] --------
// A: rows x K (lda=K), W: N rows with row stride ldw, C: rows x N.
// 128x128 block tile, BK=8, 256 threads, 8x8 per-thread microtile.
__global__ void __launch_bounds__(256, 2) sgemm_nt_bias(
    const float* __restrict__ A, const float* __restrict__ W,
    const float* __restrict__ bias, float* __restrict__ C,
    int N, int K, int ldw)
{
    __shared__ float As[8][128];
    __shared__ float Bs[8][128];
    const int tid  = threadIdx.x;
    const long row0 = (long)blockIdx.y * 128;
    const int  col0 = blockIdx.x * 128;
    const int  lr = tid >> 1;
    const int  lk = (tid & 1) * 4;
    const float* Ap = A + (row0 + lr) * (long)K + lk;
    const float* Wp = W + (long)(col0 + lr) * ldw + lk;
    const int tx = tid & 15;
    const int ty = tid >> 4;

    float acc[8][8];
    #pragma unroll
    for (int i = 0; i < 8; i++)
        #pragma unroll
        for (int j = 0; j < 8; j++) acc[i][j] = 0.f;

    for (int k0 = 0; k0 < K; k0 += 8) {
        float4 a4 = *(const float4*)(Ap + k0);
        float4 w4 = *(const float4*)(Wp + k0);
        As[lk+0][lr] = a4.x; As[lk+1][lr] = a4.y;
        As[lk+2][lr] = a4.z; As[lk+3][lr] = a4.w;
        Bs[lk+0][lr] = w4.x; Bs[lk+1][lr] = w4.y;
        Bs[lk+2][lr] = w4.z; Bs[lk+3][lr] = w4.w;
        __syncthreads();
        #pragma unroll
        for (int kk = 0; kk < 8; kk++) {
            float4 a0 = *(const float4*)&As[kk][ty*8];
            float4 a1 = *(const float4*)&As[kk][ty*8+4];
            float4 b0 = *(const float4*)&Bs[kk][tx*8];
            float4 b1 = *(const float4*)&Bs[kk][tx*8+4];
            float ra[8] = {a0.x,a0.y,a0.z,a0.w,a1.x,a1.y,a1.z,a1.w};
            float rb[8] = {b0.x,b0.y,b0.z,b0.w,b1.x,b1.y,b1.z,b1.w};
            #pragma unroll
            for (int i = 0; i < 8; i++)
                #pragma unroll
                for (int j = 0; j < 8; j++)
                    acc[i][j] += ra[i] * rb[j];
        }
        __syncthreads();
    }

    #pragma unroll
    for (int i = 0; i < 8; i++) {
        long r = row0 + ty*8 + i;
        float* cp = C + r * (long)N + col0 + tx*8;
        const float* bp = bias + col0 + tx*8;
        #pragma unroll
        for (int j = 0; j < 8; j++) cp[j] = acc[i][j] + bp[j];
    }
}

// ---------------- fused attention: softmax(Q K^T / 8) V per (b,h) ----------
// Q: (B,S,E) with head h at column h*64; K,V: (M,E) batch-independent.
// Block = 4 warps, each warp handles 4 query rows; full M=512 keys per warp.
__global__ void __launch_bounds__(128) attn_kernel(
    const float* __restrict__ Q, const float* __restrict__ Kp,
    const float* __restrict__ Vp, float* __restrict__ O)
{
    __shared__ float qs[4][4][64];
    __shared__ float ps[4][4][512];
    const int warp = threadIdx.x >> 5;
    const int lane = threadIdx.x & 31;
    const int bx   = blockIdx.x;
    const int h    = bx >> 10;          // / (B*S/16) = 1024
    const int rem  = bx & 1023;
    const int b    = rem >> 7;          // / (S/16) = 128
    const int sq0  = (rem & 127) * 16 + warp * 4;
    const long qrow0 = ((long)b * Sc + sq0) * Ec + h * 64;

    #pragma unroll
    for (int r = 0; r < 4; r++) {
        float2 q2 = *(const float2*)(Q + qrow0 + (long)r * Ec + lane * 2);
        qs[warp][r][lane*2]   = q2.x * 0.125f;   // 1/sqrt(64)
        qs[warp][r][lane*2+1] = q2.y * 0.125f;
    }
    __syncwarp();

    // pass 1: raw scores, per-row running max
    float mx0 = -1e30f, mx1 = -1e30f, mx2 = -1e30f, mx3 = -1e30f;
    const float* kb = Kp + h * 64;
    for (int i = 0; i < 16; i++) {
        int m = i*32 + lane;
        const float* kr = kb + (long)m * Ec;
        float a0 = 0.f, a1 = 0.f, a2 = 0.f, a3 = 0.f;
        #pragma unroll
        for (int d4 = 0; d4 < 16; d4++) {
            float4 k4  = *(const float4*)(kr + d4*4);
            float4 q0  = *(const float4*)&qs[warp][0][d4*4];
            float4 q1  = *(const float4*)&qs[warp][1][d4*4];
            float4 q2v = *(const float4*)&qs[warp][2][d4*4];
            float4 q3  = *(const float4*)&qs[warp][3][d4*4];
            a0 += q0.x*k4.x + q0.y*k4.y + q0.z*k4.z + q0.w*k4.w;
            a1 += q1.x*k4.x + q1.y*k4.y + q1.z*k4.z + q1.w*k4.w;
            a2 += q2v.x*k4.x + q2v.y*k4.y + q2v.z*k4.z + q2v.w*k4.w;
            a3 += q3.x*k4.x + q3.y*k4.y + q3.z*k4.z + q3.w*k4.w;
        }
        ps[warp][0][m] = a0; ps[warp][1][m] = a1;
        ps[warp][2][m] = a2; ps[warp][3][m] = a3;
        mx0 = fmaxf(mx0, a0); mx1 = fmaxf(mx1, a1);
        mx2 = fmaxf(mx2, a2); mx3 = fmaxf(mx3, a3);
    }
    #pragma unroll
    for (int o = 16; o; o >>= 1) {
        mx0 = fmaxf(mx0, __shfl_xor_sync(0xffffffffu, mx0, o));
        mx1 = fmaxf(mx1, __shfl_xor_sync(0xffffffffu, mx1, o));
        mx2 = fmaxf(mx2, __shfl_xor_sync(0xffffffffu, mx2, o));
        mx3 = fmaxf(mx3, __shfl_xor_sync(0xffffffffu, mx3, o));
    }

    // pass 2: exponentiate (own-lane slots), accumulate sums
    float sm0 = 0.f, sm1 = 0.f, sm2 = 0.f, sm3 = 0.f;
    for (int i = 0; i < 16; i++) {
        int m = i*32 + lane;
        float e0 = __expf(ps[warp][0][m] - mx0); ps[warp][0][m] = e0; sm0 += e0;
        float e1 = __expf(ps[warp][1][m] - mx1); ps[warp][1][m] = e1; sm1 += e1;
        float e2 = __expf(ps[warp][2][m] - mx2); ps[warp][2][m] = e2; sm2 += e2;
        float e3 = __expf(ps[warp][3][m] - mx3); ps[warp][3][m] = e3; sm3 += e3;
    }
    #pragma unroll
    for (int o = 16; o; o >>= 1) {
        sm0 += __shfl_xor_sync(0xffffffffu, sm0, o);
        sm1 += __shfl_xor_sync(0xffffffffu, sm1, o);
        sm2 += __shfl_xor_sync(0xffffffffu, sm2, o);
        sm3 += __shfl_xor_sync(0xffffffffu, sm3, o);
    }
    float inv0 = 1.f/sm0, inv1 = 1.f/sm1, inv2 = 1.f/sm2, inv3 = 1.f/sm3;
    __syncwarp();

    // PV: each lane owns 2 output dims for all 4 rows
    float o00=0.f,o01=0.f,o10=0.f,o11=0.f,o20=0.f,o21=0.f,o30=0.f,o31=0.f;
    const float* vb = Vp + h*64 + lane*2;
    #pragma unroll 4
    for (int m = 0; m < 512; m++) {
        float2 v2 = *(const float2*)(vb + (long)m * Ec);
        float p0 = ps[warp][0][m], p1 = ps[warp][1][m];
        float p2 = ps[warp][2][m], p3 = ps[warp][3][m];
        o00 += p0*v2.x; o01 += p0*v2.y;
        o10 += p1*v2.x; o11 += p1*v2.y;
        o20 += p2*v2.x; o21 += p2*v2.y;
        o30 += p3*v2.x; o31 += p3*v2.y;
    }
    float2 r0 = {o00*inv0, o01*inv0};
    float2 r1 = {o10*inv1, o11*inv1};
    float2 r2 = {o20*inv2, o21*inv2};
    float2 r3 = {o30*inv3, o31*inv3};
    *(float2*)(O + qrow0 + 0*Ec + lane*2) = r0;
    *(float2*)(O + qrow0 + 1*Ec + lane*2) = r1;
    *(float2*)(O + qrow0 + 2*Ec + lane*2) = r2;
    *(float2*)(O + qrow0 + 3*Ec + lane*2) = r3;
}

// ---------------- residual + LayerNorm (one row of 1024 per block) ---------
__global__ void __launch_bounds__(256) resid_ln_kernel(
    const float* __restrict__ Pr, const float* __restrict__ Res,
    const float* __restrict__ gw, const float* __restrict__ bw,
    float* __restrict__ out)
{
    __shared__ float sA[8], sB[8];
    long row = blockIdx.x;
    int t = threadIdx.x;
    long base = row * Ec + t*4;
    float4 p = *(const float4*)(Pr + base);
    float4 r = *(const float4*)(Res + base);
    float v0 = p.x+r.x, v1 = p.y+r.y, v2 = p.z+r.z, v3 = p.w+r.w;
    float s  = v0+v1+v2+v3;
    float sq = v0*v0+v1*v1+v2*v2+v3*v3;
    int lane = t & 31, wid = t >> 5;
    #pragma unroll
    for (int o = 16; o; o >>= 1) {
        s  += __shfl_xor_sync(0xffffffffu, s,  o);
        sq += __shfl_xor_sync(0xffffffffu, sq, o);
    }
    if (lane == 0) { sA[wid] = s; sB[wid] = sq; }
    __syncthreads();
    if (t < 32) {
        s  = (t < 8) ? sA[t] : 0.f;
        sq = (t < 8) ? sB[t] : 0.f;
        #pragma unroll
        for (int o = 4; o; o >>= 1) {
            s  += __shfl_xor_sync(0xffffffffu, s,  o);
            sq += __shfl_xor_sync(0xffffffffu, sq, o);
        }
        if (t == 0) { sA[0] = s; sB[0] = sq; }
    }
    __syncthreads();
    float mu  = sA[0] * (1.f/Ec);
    float var = sB[0] * (1.f/Ec) - mu*mu;
    float rs  = rsqrtf(var + 1e-5f);
    float4 g4 = *(const float4*)(gw + t*4);
    float4 b4 = *(const float4*)(bw + t*4);
    float4 o4;
    o4.x = (v0-mu)*rs*g4.x + b4.x;
    o4.y = (v1-mu)*rs*g4.y + b4.y;
    o4.z = (v2-mu)*rs*g4.z + b4.z;
    o4.w = (v3-mu)*rs*g4.w + b4.w;
    *(float4*)(out + base) = o4;
}

// ---------------- gate + blend + LayerNorm for new_mem ---------------------
__global__ void __launch_bounds__(256) newmem_ln_kernel(
    const float* __restrict__ gmem, const float* __restrict__ gupd,
    const float* __restrict__ updv, const float* __restrict__ mem,
    const float* __restrict__ gw, const float* __restrict__ bw,
    float* __restrict__ out)
{
    __shared__ float sA[8], sB[8];
    int rb = blockIdx.x;            // b*M + m
    int b  = rb >> 9;               // / 512
    int m  = rb & 511;
    int t  = threadIdx.x;
    int e  = t * 4;
    float4 gm = *(const float4*)(gmem + (long)m*Ec + e);
    float4 gu = *(const float4*)(gupd + (long)b*Ec + e);
    float4 uu = *(const float4*)(updv + (long)b*Ec + e);
    float4 mm = *(const float4*)(mem  + (long)m*Ec + e);
    float g0 = 1.f/(1.f + __expf(-(gm.x + gu.x)));
    float g1 = 1.f/(1.f + __expf(-(gm.y + gu.y)));
    float g2 = 1.f/(1.f + __expf(-(gm.z + gu.z)));
    float g3 = 1.f/(1.f + __expf(-(gm.w + gu.w)));
    float v0 = g0*uu.x + (1.f-g0)*mm.x;
    float v1 = g1*uu.y + (1.f-g1)*mm.y;
    float v2 = g2*uu.z + (1.f-g2)*mm.z;
    float v3 = g3*uu.w + (1.f-g3)*mm.w;
    float s  = v0+v1+v2+v3;
    float sq = v0*v0+v1*v1+v2*v2+v3*v3;
    int lane = t & 31, wid = t >> 5;
    #pragma unroll
    for (int o = 16; o; o >>= 1) {
        s  += __shfl_xor_sync(0xffffffffu, s,  o);
        sq += __shfl_xor_sync(0xffffffffu, sq, o);
    }
    if (lane == 0) { sA[wid] = s; sB[wid] = sq; }
    __syncthreads();
    if (t < 32) {
        s  = (t < 8) ? sA[t] : 0.f;
        sq = (t < 8) ? sB[t] : 0.f;
        #pragma unroll
        for (int o = 4; o; o >>= 1) {
            s  += __shfl_xor_sync(0xffffffffu, s,  o);
            sq += __shfl_xor_sync(0xffffffffu, sq, o);
        }
        if (t == 0) { sA[0] = s; sB[0] = sq; }
    }
    __syncthreads();
    float mu  = sA[0] * (1.f/Ec);
    float var = sB[0] * (1.f/Ec) - mu*mu;
    float rs  = rsqrtf(var + 1e-5f);
    float4 g4 = *(const float4*)(gw + e);
    float4 b4 = *(const float4*)(bw + e);
    float4 o4;
    o4.x = (v0-mu)*rs*g4.x + b4.x;
    o4.y = (v1-mu)*rs*g4.y + b4.y;
    o4.z = (v2-mu)*rs*g4.z + b4.z;
    o4.w = (v3-mu)*rs*g4.w + b4.w;
    *(float4*)(out + (long)rb*Ec + e) = o4;
}

// ---------------- wq = mean over S of query -------------------------------
__global__ void __launch_bounds__(256) wq_partial_kernel(
    const float* __restrict__ Q, float* __restrict__ part)
{
    int e = blockIdx.x * 256 + threadIdx.x;
    int b = blockIdx.y;
    int z = blockIdx.z;
    const float* p = Q + ((long)b*Sc + (long)z*256) * Ec + e;
    float s = 0.f;
    for (int i = 0; i < 256; i++) s += p[(long)i * Ec];
    part[((long)z*Bc + b)*Ec + e] = s;
}

__global__ void __launch_bounds__(256) wq_final_kernel(
    const float* __restrict__ part, float* __restrict__ wq)
{
    int e = blockIdx.x * 256 + threadIdx.x;
    int b = blockIdx.y;
    float s = 0.f;
    #pragma unroll
    for (int z = 0; z < 8; z++) s += part[((long)z*Bc + b)*Ec + e];
    wq[(long)b*Ec + e] = s * (1.f/Sc);
}

// ---------------- per-batch GEMV: y[b,j] = bias[j] + x[b,:] . W[j,:] ------
__global__ void __launch_bounds__(256) gemv_nt_kernel(
    const float* __restrict__ x, const float* __restrict__ W, long ldw,
    const float* __restrict__ bias, float* __restrict__ y)
{
    int j = blockIdx.x * 256 + threadIdx.x;
    int b = blockIdx.y;
    const float* wr = W + (long)j * ldw;
    const float* xb = x + (long)b * Ec;
    float acc = bias ? bias[j] : 0.f;
    for (int k = 0; k < Ec; k += 4) {
        float4 w4 = *(const float4*)(wr + k);
        float4 x4 = *(const float4*)(xb + k);
        acc += x4.x*w4.x + x4.y*w4.y + x4.z*w4.z + x4.w*w4.w;
    }
    y[(long)b*Ec + j] = acc;
}

// ---------------- host launcher -------------------------------------------
extern "C" void kernel_launch(void* const* d_in, const int* in_sizes, int n_in,
                              void* d_out, int out_size)
{
    const float* query   = (const float*)d_in[0];
    const float* memory  = (const float*)d_in[1];
    const float* r_in_w  = (const float*)d_in[2];
    const float* r_in_b  = (const float*)d_in[3];
    const float* r_out_w = (const float*)d_in[4];
    const float* r_out_b = (const float*)d_in[5];
    const float* w_in_w  = (const float*)d_in[6];
    const float* w_in_b  = (const float*)d_in[7];
    const float* w_out_w = (const float*)d_in[8];
    const float* w_out_b = (const float*)d_in[9];
    const float* rn_g    = (const float*)d_in[10];
    const float* rn_b    = (const float*)d_in[11];
    const float* wn_g    = (const float*)d_in[12];
    const float* wn_b    = (const float*)d_in[13];
    const float* gate_w  = (const float*)d_in[14];
    const float* gate_b  = (const float*)d_in[15];
    float* out = (float*)d_out;

    static float *pQ=nullptr,*pA,*pP,*pK,*pV,*pG,*pWP,*pWQ,*pVW,*pUP,*pGU;
    if (!pQ) {
        cudaGetSymbolAddress((void**)&pA,  g_attn);
        cudaGetSymbolAddress((void**)&pP,  g_proj);
        cudaGetSymbolAddress((void**)&pK,  g_Kp);
        cudaGetSymbolAddress((void**)&pV,  g_Vp);
        cudaGetSymbolAddress((void**)&pG,  g_gmem);
        cudaGetSymbolAddress((void**)&pWP, g_wqpart);
        cudaGetSymbolAddress((void**)&pWQ, g_wq);
        cudaGetSymbolAddress((void**)&pVW, g_vw);
        cudaGetSymbolAddress((void**)&pUP, g_upd);
        cudaGetSymbolAddress((void**)&pGU, g_gupd);
        cudaGetSymbolAddress((void**)&pQ,  g_Qp);   // last: guards init
    }

    dim3 gq(Ec/128, (Bc*Sc)/128);   // (8, 128)
    dim3 gm(Ec/128, Mc/128);        // (8, 4)

    // read path: projections
    sgemm_nt_bias<<<gq, 256>>>(query,  r_in_w,                     r_in_b,        pQ, Ec, Ec, Ec);
    sgemm_nt_bias<<<gm, 256>>>(memory, r_in_w + (size_t)Ec*Ec,     r_in_b + Ec,   pK, Ec, Ec, Ec);
    sgemm_nt_bias<<<gm, 256>>>(memory, r_in_w + (size_t)2*Ec*Ec,   r_in_b + 2*Ec, pV, Ec, Ec, Ec);
    // gate (batch-independent half), overlappable with attention chain
    sgemm_nt_bias<<<gm, 256>>>(memory, gate_w, gate_b, pG, Ec, Ec, 2*Ec);

    // attention + out-proj + residual LN -> mem_out
    attn_kernel<<<Bc*Hc*Sc/16, 128>>>(pQ, pK, pV, pA);
    sgemm_nt_bias<<<gq, 256>>>(pA, r_out_w, r_out_b, pP, Ec, Ec, Ec);
    resid_ln_kernel<<<Bc*Sc, 256>>>(pP, query, rn_g, rn_b, out);

    // write path: softmax over length-1 keys == 1, so only the V/out-proj chain matters
    wq_partial_kernel<<<dim3(Ec/256, Bc, 8), 256>>>(query, pWP);
    wq_final_kernel  <<<dim3(Ec/256, Bc),    256>>>(pWP, pWQ);
    gemv_nt_kernel<<<dim3(Ec/256, Bc), 256>>>(pWQ, w_in_w + (size_t)2*Ec*Ec, Ec,   w_in_b + 2*Ec, pVW);
    gemv_nt_kernel<<<dim3(Ec/256, Bc), 256>>>(pVW, w_out_w,                  Ec,   w_out_b,       pUP);
    gemv_nt_kernel<<<dim3(Ec/256, Bc), 256>>>(pUP, gate_w + Ec,              2*Ec, nullptr,       pGU);

    // gate + blend + LN -> new_mem
    newmem_ln_kernel<<<Bc*Mc, 256>>>(pG, pGU, pUP, memory, wn_g, wn_b,
                                     out + (size_t)Bc*Sc*Ec);
}

// round 5
// speedup vs baseline: 3.5958x; 3.5958x over previous
#include <cuda_runtime.h>
#include <cuda_bf16.h>
#include <cstdint>

#define Bc 8
#define Sc 2048
#define Mc 512
#define Ec 1024
#define Hc 16
#define Dc 64
#define ZNc (Bc*Hc)

// ---------------- scratch (static device globals; no runtime allocation) ----
__device__ float g_Qp  [(size_t)Bc*Sc*Ec];          // 64 MB
__device__ float g_attn[(size_t)Bc*Sc*Ec];          // 64 MB
__device__ float g_proj[(size_t)Bc*Sc*Ec];          // 64 MB
__device__ float g_Kp  [Mc*Ec];
__device__ float g_Vp  [Mc*Ec];
__device__ float g_gmem[Mc*Ec];
__device__ float g_scores[(size_t)ZNc*Sc*Mc];       // 512 MB fp32 logits
__device__ __nv_bfloat16 g_Phi[(size_t)ZNc*Sc*Mc]; // 256 MB
__device__ __nv_bfloat16 g_Plo[(size_t)ZNc*Sc*Mc]; // 256 MB
__device__ __nv_bfloat16 g_Vthi[Hc*Dc*Mc];
__device__ __nv_bfloat16 g_Vtlo[Hc*Dc*Mc];
__device__ float g_wqpart[8*Bc*Ec];
__device__ float g_wq  [Bc*Ec];
__device__ float g_vw  [Bc*Ec];
__device__ float g_upd [Bc*Ec];
__device__ float g_gupd[Bc*Ec];

// ---------------- helpers ---------------------------------------------------
__device__ __forceinline__ uint32_t smem_u32(const void* p) {
    uint32_t a;
    asm("{ .reg .u64 t; cvta.to.shared.u64 t, %1; cvt.u32.u64 %0, t; }"
        : "=r"(a) : "l"(p));
    return a;
}
// 64-byte-row tile swizzle: XOR byte bits (7,8) onto (4,5)
#define SWZ(off) ((off) ^ (((off) >> 3) & 0x30))

__device__ __forceinline__ void ldm_x4(uint32_t* r, uint32_t addr) {
    asm volatile("ldmatrix.sync.aligned.m8n8.x4.shared.b16 {%0,%1,%2,%3}, [%4];"
        : "=r"(r[0]), "=r"(r[1]), "=r"(r[2]), "=r"(r[3]) : "r"(addr));
}
__device__ __forceinline__ void mma16816(float* d, const uint32_t* a,
                                         const uint32_t* b) {
    asm volatile(
        "mma.sync.aligned.m16n8k16.row.col.f32.bf16.bf16.f32 "
        "{%0,%1,%2,%3}, {%4,%5,%6,%7}, {%8,%9}, {%0,%1,%2,%3};"
        : "+f"(d[0]), "+f"(d[1]), "+f"(d[2]), "+f"(d[3])
        : "r"(a[0]), "r"(a[1]), "r"(a[2]), "r"(a[3]), "r"(b[0]), "r"(b[1]));
}
__device__ __forceinline__ uint32_t pack_split(float a, float b, uint32_t& lo) {
    __nv_bfloat16 ah = __float2bfloat16(a);
    __nv_bfloat16 bh = __float2bfloat16(b);
    __nv_bfloat16 al = __float2bfloat16(a - __bfloat162float(ah));
    __nv_bfloat16 bl = __float2bfloat16(b - __bfloat162float(bh));
    lo = (uint32_t)__bfloat16_as_ushort(al)
       | ((uint32_t)__bfloat16_as_ushort(bl) << 16);
    return (uint32_t)__bfloat16_as_ushort(ah)
         | ((uint32_t)__bfloat16_as_ushort(bh) << 16);
}

// ---------------- tile load / store stages ----------------------------------
// MODE0 global fetch: TR rows x 32 fp32, thread slots = TR*2 (row, 16-col half)
template<int TR>
__device__ __forceinline__ void ldg_f32(const float* __restrict__ src, int ld,
                                        int k0, float4* r, int tid) {
    if (TR == 64 && tid >= 128) return;
    int row = tid >> 1, half = tid & 1;
    const float* p = src + (long)row * ld + k0 + half * 16;
    r[0] = *(const float4*)p;       r[1] = *(const float4*)(p + 4);
    r[2] = *(const float4*)(p + 8); r[3] = *(const float4*)(p + 12);
}
template<int TR>
__device__ __forceinline__ void sts_split(char* hi, char* lo, const float4* r,
                                          float sc, int tid) {
    if (TR == 64 && tid >= 128) return;
    int row = tid >> 1, half = tid & 1;
    #pragma unroll
    for (int q = 0; q < 2; q++) {
        float f[8] = { r[2*q].x, r[2*q].y, r[2*q].z, r[2*q].w,
                       r[2*q+1].x, r[2*q+1].y, r[2*q+1].z, r[2*q+1].w };
        uint32_t h[4], l[4];
        #pragma unroll
        for (int j = 0; j < 4; j++)
            h[j] = pack_split(f[2*j] * sc, f[2*j+1] * sc, l[j]);
        uint32_t off = SWZ((uint32_t)(row * 64 + half * 32 + q * 16));
        *(uint4*)(hi + off) = make_uint4(h[0], h[1], h[2], h[3]);
        *(uint4*)(lo + off) = make_uint4(l[0], l[1], l[2], l[3]);
    }
}
// MODE1: TR rows x 32 bf16, 16B chunks, TR/64 chunks per thread
template<int TR>
__device__ __forceinline__ void ldg_bf16(const __nv_bfloat16* __restrict__ src,
                                         int ld, int k0, uint4* r, int tid) {
    #pragma unroll
    for (int i = 0; i < TR/64; i++) {
        int c = tid + 256*i; int row = c >> 2, q = c & 3;
        r[i] = *(const uint4*)(src + (long)row * ld + k0 + q * 8);
    }
}
template<int TR>
__device__ __forceinline__ void sts_bf16(char* dst, const uint4* r, int tid) {
    #pragma unroll
    for (int i = 0; i < TR/64; i++) {
        int c = tid + 256*i; int row = c >> 2, q = c & 3;
        *(uint4*)(dst + SWZ((uint32_t)(row * 64 + q * 16))) = r[i];
    }
}

// ---------------- warp-MMA NT GEMM: C[r,c] = sum_k A[r,k]*B[c,k] (+bias) ----
// MODE 0: A,B fp32 (split on the fly, 3 MMAs/product). MODE 1: presplit bf16.
// Block 128 x NT, BK=32, 8 warps (4 m x 2 n), double-buffered smem.
template<int NT, int MODE>
__global__ void __launch_bounds__(256) mma_gemm(
    const void* Ap, const void* Ap2, const void* Bp, const void* Bp2,
    const float* __restrict__ bias, float* __restrict__ C,
    int K, int lda, int ldb, int ldc,
    long aStrB, long aStrH, long bStrB, long bStrH, long cStrB, long cStrH,
    float ascale)
{
    extern __shared__ char sm[];
    constexpr int WARP_N = NT / 2;
    constexpr int N8T    = WARP_N / 8;
    constexpr int STAGE  = 16384 + NT * 128;  // Ahi+Alo (16K) + Bhi+Blo

    int tid = threadIdx.x, wid = tid >> 5, lane = tid & 31;
    int wm = wid & 3, wn = wid >> 2;
    int z = blockIdx.z;
    long za = (long)(z >> 4) * aStrB + (long)(z & 15) * aStrH;
    long zb = (long)(z >> 4) * bStrB + (long)(z & 15) * bStrH;
    long zc = (long)(z >> 4) * cStrB + (long)(z & 15) * cStrH;
    long row0 = (long)blockIdx.y * 128;
    int  col0 = blockIdx.x * NT;

    const float* A32 = nullptr; const float* B32 = nullptr;
    const __nv_bfloat16 *A16h = nullptr, *A16l = nullptr,
                        *B16h = nullptr, *B16l = nullptr;
    if (MODE == 0) {
        A32 = (const float*)Ap + za + row0 * lda;
        B32 = (const float*)Bp + zb + (long)col0 * ldb;
    } else {
        A16h = (const __nv_bfloat16*)Ap  + za + row0 * lda;
        A16l = (const __nv_bfloat16*)Ap2 + za + row0 * lda;
        B16h = (const __nv_bfloat16*)Bp  + zb + (long)col0 * ldb;
        B16l = (const __nv_bfloat16*)Bp2 + zb + (long)col0 * ldb;
    }

    float acc[2][N8T][4];
    #pragma unroll
    for (int mt = 0; mt < 2; mt++)
        #pragma unroll
        for (int nt = 0; nt < N8T; nt++)
            #pragma unroll
            for (int j = 0; j < 4; j++) acc[mt][nt][j] = 0.f;

    float4 ra[4], rb[4];
    uint4 sah[2], sal[2], sbh[NT/64 > 0 ? NT/64 : 1], sbl[NT/64 > 0 ? NT/64 : 1];

    const int nCh = K >> 5;
    if (MODE == 0) {
        ldg_f32<128>(A32, lda, 0, ra, tid);
        ldg_f32<NT>(B32, ldb, 0, rb, tid);
    } else {
        ldg_bf16<128>(A16h, lda, 0, sah, tid);
        ldg_bf16<128>(A16l, lda, 0, sal, tid);
        ldg_bf16<NT>(B16h, ldb, 0, sbh, tid);
        ldg_bf16<NT>(B16l, ldb, 0, sbl, tid);
    }

    for (int c = 0; c < nCh; c++) {
        char* bufAh = sm + (c & 1) * STAGE;
        char* bufAl = bufAh + 8192;
        char* bufBh = bufAh + 16384;
        char* bufBl = bufBh + NT * 64;
        if (MODE == 0) {
            sts_split<128>(bufAh, bufAl, ra, ascale, tid);
            sts_split<NT>(bufBh, bufBl, rb, 1.f, tid);
            if (c + 1 < nCh) {
                ldg_f32<128>(A32, lda, (c+1)*32, ra, tid);
                ldg_f32<NT>(B32, ldb, (c+1)*32, rb, tid);
            }
        } else {
            sts_bf16<128>(bufAh, sah, tid);
            sts_bf16<128>(bufAl, sal, tid);
            sts_bf16<NT>(bufBh, sbh, tid);
            sts_bf16<NT>(bufBl, sbl, tid);
            if (c + 1 < nCh) {
                ldg_bf16<128>(A16h, lda, (c+1)*32, sah, tid);
                ldg_bf16<128>(A16l, lda, (c+1)*32, sal, tid);
                ldg_bf16<NT>(B16h, ldb, (c+1)*32, sbh, tid);
                ldg_bf16<NT>(B16l, ldb, (c+1)*32, sbl, tid);
            }
        }
        __syncthreads();

        uint32_t baseAh = smem_u32(bufAh);
        uint32_t baseAl = baseAh + 8192;
        uint32_t baseBh = baseAh + 16384;
        uint32_t baseBl = baseBh + NT * 64;
        int r = lane & 7, t = lane >> 3;

        #pragma unroll
        for (int ks = 0; ks < 2; ks++) {
            int kb = ks * 32;   // byte offset of k16 step
            uint32_t bh[2*N8T], bl[2*N8T];
            #pragma unroll
            for (int p = 0; p < N8T/2; p++) {
                int brow = wn * WARP_N + p * 16 + ((t >> 1) << 3) + r;
                int bcol = kb + ((t & 1) << 4);
                uint32_t o = SWZ((uint32_t)(brow * 64 + bcol));
                ldm_x4(&bh[p*4], baseBh + o);
                ldm_x4(&bl[p*4], baseBl + o);
            }
            #pragma unroll
            for (int mt = 0; mt < 2; mt++) {
                int arow = wm * 32 + mt * 16 + ((t & 1) << 3) + r;
                int acol = kb + ((t >> 1) << 4);
                uint32_t o = SWZ((uint32_t)(arow * 64 + acol));
                uint32_t ah4[4], al4[4];
                ldm_x4(ah4, baseAh + o);
                ldm_x4(al4, baseAl + o);
                #pragma unroll
                for (int nt = 0; nt < N8T; nt++) {
                    mma16816(acc[mt][nt], ah4, &bh[nt*2]);
                    mma16816(acc[mt][nt], ah4, &bl[nt*2]);
                    mma16816(acc[mt][nt], al4, &bh[nt*2]);
                }
            }
        }
        // single barrier per chunk: next STS targets the other buffer
    }

    // epilogue: fragment-direct stores (+bias)
    long crow = row0 + wm * 32 + (lane >> 2);
    #pragma unroll
    for (int mt = 0; mt < 2; mt++) {
        #pragma unroll
        for (int nt = 0; nt < N8T; nt++) {
            int cc = col0 + wn * WARP_N + nt * 8 + ((lane & 3) << 1);
            float b0 = 0.f, b1 = 0.f;
            if (bias) { b0 = bias[cc]; b1 = bias[cc + 1]; }
            long rr = crow + mt * 16;
            float2 v0 = make_float2(acc[mt][nt][0] + b0, acc[mt][nt][1] + b1);
            float2 v1 = make_float2(acc[mt][nt][2] + b0, acc[mt][nt][3] + b1);
            *(float2*)(C + zc + rr * (long)ldc + cc) = v0;
            *(float2*)(C + zc + (rr + 8) * (long)ldc + cc) = v1;
        }
    }
}

// ---------------- softmax over M=512, fp32 in, split bf16 out --------------
__global__ void __launch_bounds__(256) softmax_kernel(
    const float* __restrict__ S, __nv_bfloat16* __restrict__ Phi,
    __nv_bfloat16* __restrict__ Plo)
{
    long row = (long)blockIdx.x * 8 + (threadIdx.x >> 5);
    int lane = threadIdx.x & 31;
    const float* sr = S + row * Mc;
    float v[16];
    float mx = -1e30f;
    #pragma unroll
    for (int j = 0; j < 4; j++) {
        float4 x = *(const float4*)(sr + j * 128 + lane * 4);
        v[4*j] = x.x; v[4*j+1] = x.y; v[4*j+2] = x.z; v[4*j+3] = x.w;
        mx = fmaxf(mx, fmaxf(fmaxf(x.x, x.y), fmaxf(x.z, x.w)));
    }
    #pragma unroll
    for (int o = 16; o; o >>= 1) mx = fmaxf(mx, __shfl_xor_sync(0xffffffffu, mx, o));
    float sm = 0.f;
    #pragma unroll
    for (int i = 0; i < 16; i++) { v[i] = __expf(v[i] - mx); sm += v[i]; }
    #pragma unroll
    for (int o = 16; o; o >>= 1) sm += __shfl_xor_sync(0xffffffffu, sm, o);
    float inv = 1.f / sm;
    #pragma unroll
    for (int j = 0; j < 4; j++) {
        uint32_t h[2], l[2];
        #pragma unroll
        for (int q = 0; q < 2; q++)
            h[q] = pack_split(v[4*j+2*q] * inv, v[4*j+2*q+1] * inv, l[q]);
        *(uint2*)(Phi + row * Mc + j * 128 + lane * 4) = make_uint2(h[0], h[1]);
        *(uint2*)(Plo + row * Mc + j * 128 + lane * 4) = make_uint2(l[0], l[1]);
    }
}

// ---------------- V transpose: (M,E) fp32 -> per-head (D,M) split bf16 -----
__global__ void vtrans_kernel(const float* __restrict__ V,
                              __nv_bfloat16* __restrict__ hi,
                              __nv_bfloat16* __restrict__ lo)
{
    __shared__ float t[32][33];
    int m0 = blockIdx.x * 32;
    int h  = blockIdx.y;
    int tx = threadIdx.x, ty = threadIdx.y;  // (32,8)
    for (int d0 = 0; d0 < 64; d0 += 32) {
        for (int r = ty; r < 32; r += 8)
            t[r][tx] = V[(long)(m0 + r) * Ec + h * 64 + d0 + tx];
        __syncthreads();
        for (int r = ty; r < 32; r += 8) {
            float x = t[tx][r];
            __nv_bfloat16 xh = __float2bfloat16(x);
            long o = (long)h * Dc * Mc + (long)(d0 + r) * Mc + m0 + tx;
            hi[o] = xh;
            lo[o] = __float2bfloat16(x - __bfloat162float(xh));
        }
        __syncthreads();
    }
}

// ---------------- residual + LayerNorm -------------------------------------
__global__ void __launch_bounds__(256) resid_ln_kernel(
    const float* __restrict__ Pr, const float* __restrict__ Res,
    const float* __restrict__ gw, const float* __restrict__ bw,
    float* __restrict__ out)
{
    __shared__ float sA[8], sB[8];
    long row = blockIdx.x;
    int t = threadIdx.x;
    long base = row * Ec + t * 4;
    float4 p = *(const float4*)(Pr + base);
    float4 r = *(const float4*)(Res + base);
    float v0 = p.x+r.x, v1 = p.y+r.y, v2 = p.z+r.z, v3 = p.w+r.w;
    float s  = v0+v1+v2+v3;
    float sq = v0*v0+v1*v1+v2*v2+v3*v3;
    int lane = t & 31, wid = t >> 5;
    #pragma unroll
    for (int o = 16; o; o >>= 1) {
        s  += __shfl_xor_sync(0xffffffffu, s,  o);
        sq += __shfl_xor_sync(0xffffffffu, sq, o);
    }
    if (lane == 0) { sA[wid] = s; sB[wid] = sq; }
    __syncthreads();
    if (t < 32) {
        s  = (t < 8) ? sA[t] : 0.f;
        sq = (t < 8) ? sB[t] : 0.f;
        #pragma unroll
        for (int o = 4; o; o >>= 1) {
            s  += __shfl_xor_sync(0xffffffffu, s,  o);
            sq += __shfl_xor_sync(0xffffffffu, sq, o);
        }
        if (t == 0) { sA[0] = s; sB[0] = sq; }
    }
    __syncthreads();
    float mu  = sA[0] * (1.f/Ec);
    float var = sB[0] * (1.f/Ec) - mu*mu;
    float rs  = rsqrtf(var + 1e-5f);
    float4 g4 = *(const float4*)(gw + t*4);
    float4 b4 = *(const float4*)(bw + t*4);
    float4 o4;
    o4.x = (v0-mu)*rs*g4.x + b4.x;
    o4.y = (v1-mu)*rs*g4.y + b4.y;
    o4.z = (v2-mu)*rs*g4.z + b4.z;
    o4.w = (v3-mu)*rs*g4.w + b4.w;
    *(float4*)(out + base) = o4;
}

// ---------------- gate + blend + LayerNorm ---------------------------------
__global__ void __launch_bounds__(256) newmem_ln_kernel(
    const float* __restrict__ gmem, const float* __restrict__ gupd,
    const float* __restrict__ updv, const float* __restrict__ mem,
    const float* __restrict__ gw, const float* __restrict__ bw,
    float* __restrict__ out)
{
    __shared__ float sA[8], sB[8];
    int rb = blockIdx.x;
    int b  = rb >> 9;
    int m  = rb & 511;
    int t  = threadIdx.x;
    int e  = t * 4;
    float4 gm = *(const float4*)(gmem + (long)m*Ec + e);
    float4 gu = *(const float4*)(gupd + (long)b*Ec + e);
    float4 uu = *(const float4*)(updv + (long)b*Ec + e);
    float4 mm = *(const float4*)(mem  + (long)m*Ec + e);
    float g0 = 1.f/(1.f + __expf(-(gm.x + gu.x)));
    float g1 = 1.f/(1.f + __expf(-(gm.y + gu.y)));
    float g2 = 1.f/(1.f + __expf(-(gm.z + gu.z)));
    float g3 = 1.f/(1.f + __expf(-(gm.w + gu.w)));
    float v0 = g0*uu.x + (1.f-g0)*mm.x;
    float v1 = g1*uu.y + (1.f-g1)*mm.y;
    float v2 = g2*uu.z + (1.f-g2)*mm.z;
    float v3 = g3*uu.w + (1.f-g3)*mm.w;
    float s  = v0+v1+v2+v3;
    float sq = v0*v0+v1*v1+v2*v2+v3*v3;
    int lane = t & 31, wid = t >> 5;
    #pragma unroll
    for (int o = 16; o; o >>= 1) {
        s  += __shfl_xor_sync(0xffffffffu, s,  o);
        sq += __shfl_xor_sync(0xffffffffu, sq, o);
    }
    if (lane == 0) { sA[wid] = s; sB[wid] = sq; }
    __syncthreads();
    if (t < 32) {
        s  = (t < 8) ? sA[t] : 0.f;
        sq = (t < 8) ? sB[t] : 0.f;
        #pragma unroll
        for (int o = 4; o; o >>= 1) {
            s  += __shfl_xor_sync(0xffffffffu, s,  o);
            sq += __shfl_xor_sync(0xffffffffu, sq, o);
        }
        if (t == 0) { sA[0] = s; sB[0] = sq; }
    }
    __syncthreads();
    float mu  = sA[0] * (1.f/Ec);
    float var = sB[0] * (1.f/Ec) - mu*mu;
    float rs  = rsqrtf(var + 1e-5f);
    float4 g4 = *(const float4*)(gw + e);
    float4 b4 = *(const float4*)(bw + e);
    float4 o4;
    o4.x = (v0-mu)*rs*g4.x + b4.x;
    o4.y = (v1-mu)*rs*g4.y + b4.y;
    o4.z = (v2-mu)*rs*g4.z + b4.z;
    o4.w = (v3-mu)*rs*g4.w + b4.w;
    *(float4*)(out + (long)rb*Ec + e) = o4;
}

// ---------------- wq = mean over S ------------------------------------------
__global__ void __launch_bounds__(256) wq_partial_kernel(
    const float* __restrict__ Q, float* __restrict__ part)
{
    int e = blockIdx.x * 256 + threadIdx.x;
    int b = blockIdx.y;
    int z = blockIdx.z;
    const float* p = Q + ((long)b*Sc + (long)z*256) * Ec + e;
    float s = 0.f;
    for (int i = 0; i < 256; i++) s += p[(long)i * Ec];
    part[((long)z*Bc + b)*Ec + e] = s;
}
__global__ void __launch_bounds__(256) wq_final_kernel(
    const float* __restrict__ part, float* __restrict__ wq)
{
    int e = blockIdx.x * 256 + threadIdx.x;
    int b = blockIdx.y;
    float s = 0.f;
    #pragma unroll
    for (int z = 0; z < 8; z++) s += part[((long)z*Bc + b)*Ec + e];
    wq[(long)b*Ec + e] = s * (1.f/Sc);
}

// ---------------- per-batch GEMV -------------------------------------------
__global__ void __launch_bounds__(256) gemv_nt_kernel(
    const float* __restrict__ x, const float* __restrict__ W, long ldw,
    const float* __restrict__ bias, float* __restrict__ y)
{
    int j = blockIdx.x * 256 + threadIdx.x;
    int b = blockIdx.y;
    const float* wr = W + (long)j * ldw;
    const float* xb = x + (long)b * Ec;
    float acc = bias ? bias[j] : 0.f;
    for (int k = 0; k < Ec; k += 4) {
        float4 w4 = *(const float4*)(wr + k);
        float4 x4 = *(const float4*)(xb + k);
        acc += x4.x*w4.x + x4.y*w4.y + x4.z*w4.z + x4.w*w4.w;
    }
    y[(long)b*Ec + j] = acc;
}

// ---------------- host launcher --------------------------------------------
extern "C" void kernel_launch(void* const* d_in, const int* in_sizes, int n_in,
                              void* d_out, int out_size)
{
    const float* query   = (const float*)d_in[0];
    const float* memory  = (const float*)d_in[1];
    const float* r_in_w  = (const float*)d_in[2];
    const float* r_in_b  = (const float*)d_in[3];
    const float* r_out_w = (const float*)d_in[4];
    const float* r_out_b = (const float*)d_in[5];
    const float* w_in_w  = (const float*)d_in[6];
    const float* w_in_b  = (const float*)d_in[7];
    const float* w_out_w = (const float*)d_in[8];
    const float* w_out_b = (const float*)d_in[9];
    const float* rn_g    = (const float*)d_in[10];
    const float* rn_b    = (const float*)d_in[11];
    const float* wn_g    = (const float*)d_in[12];
    const float* wn_b    = (const float*)d_in[13];
    const float* gate_w  = (const float*)d_in[14];
    const float* gate_b  = (const float*)d_in[15];
    float* out = (float*)d_out;

    constexpr int SMEM128 = 2 * (16384 + 128 * 128);  // 65536
    constexpr int SMEM64  = 2 * (16384 + 64 * 128);   // 49152

    static float *pQ = nullptr, *pA, *pP, *pK, *pV, *pG, *pS,
                 *pWP, *pWQ, *pVW, *pUP, *pGU;
    static __nv_bfloat16 *pPhi, *pPlo, *pVthi, *pVtlo;
    if (!pQ) {
        cudaGetSymbolAddress((void**)&pA,   g_attn);
        cudaGetSymbolAddress((void**)&pP,   g_proj);
        cudaGetSymbolAddress((void**)&pK,   g_Kp);
        cudaGetSymbolAddress((void**)&pV,   g_Vp);
        cudaGetSymbolAddress((void**)&pG,   g_gmem);
        cudaGetSymbolAddress((void**)&pS,   g_scores);
        cudaGetSymbolAddress((void**)&pPhi, g_Phi);
        cudaGetSymbolAddress((void**)&pPlo, g_Plo);
        cudaGetSymbolAddress((void**)&pVthi,g_Vthi);
        cudaGetSymbolAddress((void**)&pVtlo,g_Vtlo);
        cudaGetSymbolAddress((void**)&pWP,  g_wqpart);
        cudaGetSymbolAddress((void**)&pWQ,  g_wq);
        cudaGetSymbolAddress((void**)&pVW,  g_vw);
        cudaGetSymbolAddress((void**)&pUP,  g_upd);
        cudaGetSymbolAddress((void**)&pGU,  g_gupd);
        cudaFuncSetAttribute(mma_gemm<128,0>,
            cudaFuncAttributeMaxDynamicSharedMemorySize, SMEM128);
        cudaFuncSetAttribute(mma_gemm<64,1>,
            cudaFuncAttributeMaxDynamicSharedMemorySize, SMEM64);
        cudaGetSymbolAddress((void**)&pQ,   g_Qp);   // last: guards init
    }

    // --- projections + gate (split-bf16 tensor cores) ---
    mma_gemm<128,0><<<dim3(8,128,1), 256, SMEM128>>>(
        query, nullptr, r_in_w, nullptr, r_in_b, pQ,
        Ec, Ec, Ec, Ec, 0,0,0,0,0,0, 1.f);
    mma_gemm<128,0><<<dim3(8,4,1), 256, SMEM128>>>(
        memory, nullptr, r_in_w + (size_t)Ec*Ec, nullptr, r_in_b + Ec, pK,
        Ec, Ec, Ec, Ec, 0,0,0,0,0,0, 1.f);
    mma_gemm<128,0><<<dim3(8,4,1), 256, SMEM128>>>(
        memory, nullptr, r_in_w + (size_t)2*Ec*Ec, nullptr, r_in_b + 2*Ec, pV,
        Ec, Ec, Ec, Ec, 0,0,0,0,0,0, 1.f);
    mma_gemm<128,0><<<dim3(8,4,1), 256, SMEM128>>>(
        memory, nullptr, gate_w, nullptr, gate_b, pG,
        Ec, Ec, 2*Ec, Ec, 0,0,0,0,0,0, 1.f);

    // --- attention: scores -> softmax(split P) -> P@V^T ---
    vtrans_kernel<<<dim3(Mc/32, Hc), dim3(32,8)>>>(pV, pVthi, pVtlo);
    mma_gemm<128,0><<<dim3(4,16,ZNc), 256, SMEM128>>>(
        pQ, nullptr, pK, nullptr, nullptr, pS,
        Dc, Ec, Ec, Mc,
        (long)Sc*Ec, 64, 0, 64, (long)Hc*Sc*Mc, (long)Sc*Mc, 0.125f);
    softmax_kernel<<<(ZNc*Sc)/8, 256>>>(pS, pPhi, pPlo);
    mma_gemm<64,1><<<dim3(1,16,ZNc), 256, SMEM64>>>(
        pPhi, pPlo, pVthi, pVtlo, nullptr, pA,
        Mc, Mc, Mc, Ec,
        (long)Hc*Sc*Mc, (long)Sc*Mc, 0, (long)Dc*Mc, (long)Sc*Ec, 64, 1.f);

    // --- out-proj + residual LN -> mem_out ---
    mma_gemm<128,0><<<dim3(8,128,1), 256, SMEM128>>>(
        pA, nullptr, r_out_w, nullptr, r_out_b, pP,
        Ec, Ec, Ec, Ec, 0,0,0,0,0,0, 1.f);
    resid_ln_kernel<<<Bc*Sc, 256>>>(pP, query, rn_g, rn_b, out);

    // --- write path (softmax over length-1 keys == 1) ---
    wq_partial_kernel<<<dim3(Ec/256, Bc, 8), 256>>>(query, pWP);
    wq_final_kernel  <<<dim3(Ec/256, Bc),    256>>>(pWP, pWQ);
    gemv_nt_kernel<<<dim3(Ec/256, Bc), 256>>>(pWQ, w_in_w + (size_t)2*Ec*Ec, Ec,   w_in_b + 2*Ec, pVW);
    gemv_nt_kernel<<<dim3(Ec/256, Bc), 256>>>(pVW, w_out_w,                  Ec,   w_out_b,       pUP);
    gemv_nt_kernel<<<dim3(Ec/256, Bc), 256>>>(pUP, gate_w + Ec,              2*Ec, nullptr,       pGU);
    newmem_ln_kernel<<<Bc*Mc, 256>>>(pG, pGU, pUP, memory, wn_g, wn_b,
                                     out + (size_t)Bc*Sc*Ec);
}

// round 6
// speedup vs baseline: 3.6004x; 1.0013x over previous
#include <cuda_runtime.h>
#include <cuda_bf16.h>
#include <cstdint>

#define Bc 8
#define Sc 2048
#define Mc 512
#define Ec 1024
#define Hc 16
#define Dc 64
#define ZNc (Bc*Hc)

// ---------------- scratch (static device globals; no runtime allocation) ----
__device__ float g_Qp  [(size_t)Bc*Sc*Ec];          // 64 MB
__device__ float g_attn[(size_t)Bc*Sc*Ec];          // 64 MB
__device__ float g_proj[(size_t)Bc*Sc*Ec];          // 64 MB
__device__ float g_Kp  [Mc*Ec];
__device__ float g_Vp  [Mc*Ec];
__device__ float g_gmem[Mc*Ec];
__device__ float g_scores[(size_t)ZNc*Sc*Mc];       // 512 MB fp32 logits
__device__ __nv_bfloat16 g_Phi[(size_t)ZNc*Sc*Mc]; // 256 MB
__device__ __nv_bfloat16 g_Plo[(size_t)ZNc*Sc*Mc]; // 256 MB
__device__ __nv_bfloat16 g_Vthi[Hc*Dc*Mc];
__device__ __nv_bfloat16 g_Vtlo[Hc*Dc*Mc];
__device__ float g_wqpart[8*Bc*Ec];
__device__ float g_wq  [Bc*Ec];
__device__ float g_vw  [Bc*Ec];
__device__ float g_upd [Bc*Ec];
__device__ float g_gupd[Bc*Ec];

// ---------------- helpers ---------------------------------------------------
__device__ __forceinline__ uint32_t smem_u32(const void* p) {
    uint32_t a;
    asm("{ .reg .u64 t; cvta.to.shared.u64 t, %1; cvt.u32.u64 %0, t; }"
        : "=r"(a) : "l"(p));
    return a;
}
// 64-byte-row tile swizzle: XOR byte bits (7,8) onto (4,5)
#define SWZ(off) ((off) ^ (((off) >> 3) & 0x30))

__device__ __forceinline__ void ldm_x4(uint32_t* r, uint32_t addr) {
    asm volatile("ldmatrix.sync.aligned.m8n8.x4.shared.b16 {%0,%1,%2,%3}, [%4];"
        : "=r"(r[0]), "=r"(r[1]), "=r"(r[2]), "=r"(r[3]) : "r"(addr));
}
__device__ __forceinline__ void mma16816(float* d, const uint32_t* a,
                                         const uint32_t* b) {
    asm volatile(
        "mma.sync.aligned.m16n8k16.row.col.f32.bf16.bf16.f32 "
        "{%0,%1,%2,%3}, {%4,%5,%6,%7}, {%8,%9}, {%0,%1,%2,%3};"
        : "+f"(d[0]), "+f"(d[1]), "+f"(d[2]), "+f"(d[3])
        : "r"(a[0]), "r"(a[1]), "r"(a[2]), "r"(a[3]), "r"(b[0]), "r"(b[1]));
}
__device__ __forceinline__ uint32_t pack_split(float a, float b, uint32_t& lo) {
    __nv_bfloat16 ah = __float2bfloat16(a);
    __nv_bfloat16 bh = __float2bfloat16(b);
    __nv_bfloat16 al = __float2bfloat16(a - __bfloat162float(ah));
    __nv_bfloat16 bl = __float2bfloat16(b - __bfloat162float(bh));
    lo = (uint32_t)__bfloat16_as_ushort(al)
       | ((uint32_t)__bfloat16_as_ushort(bl) << 16);
    return (uint32_t)__bfloat16_as_ushort(ah)
         | ((uint32_t)__bfloat16_as_ushort(bh) << 16);
}

// ---------------- tile load / store stages ----------------------------------
// MODE0 global fetch: TR rows x 32 fp32, thread slots = TR*2 (row, 16-col half)
template<int TR>
__device__ __forceinline__ void ldg_f32(const float* __restrict__ src, int ld,
                                        int k0, float4* r, int tid) {
    if (TR == 64 && tid >= 128) return;
    int row = tid >> 1, half = tid & 1;
    const float* p = src + (long)row * ld + k0 + half * 16;
    r[0] = *(const float4*)p;       r[1] = *(const float4*)(p + 4);
    r[2] = *(const float4*)(p + 8); r[3] = *(const float4*)(p + 12);
}
template<int TR>
__device__ __forceinline__ void sts_split(char* hi, char* lo, const float4* r,
                                          float sc, int tid) {
    if (TR == 64 && tid >= 128) return;
    int row = tid >> 1, half = tid & 1;
    #pragma unroll
    for (int q = 0; q < 2; q++) {
        float f[8] = { r[2*q].x, r[2*q].y, r[2*q].z, r[2*q].w,
                       r[2*q+1].x, r[2*q+1].y, r[2*q+1].z, r[2*q+1].w };
        uint32_t h[4], l[4];
        #pragma unroll
        for (int j = 0; j < 4; j++)
            h[j] = pack_split(f[2*j] * sc, f[2*j+1] * sc, l[j]);
        uint32_t off = SWZ((uint32_t)(row * 64 + half * 32 + q * 16));
        *(uint4*)(hi + off) = make_uint4(h[0], h[1], h[2], h[3]);
        *(uint4*)(lo + off) = make_uint4(l[0], l[1], l[2], l[3]);
    }
}
// MODE1: TR rows x 32 bf16, 16B chunks, TR/64 chunks per thread
template<int TR>
__device__ __forceinline__ void ldg_bf16(const __nv_bfloat16* __restrict__ src,
                                         int ld, int k0, uint4* r, int tid) {
    #pragma unroll
    for (int i = 0; i < TR/64; i++) {
        int c = tid + 256*i; int row = c >> 2, q = c & 3;
        r[i] = *(const uint4*)(src + (long)row * ld + k0 + q * 8);
    }
}
template<int TR>
__device__ __forceinline__ void sts_bf16(char* dst, const uint4* r, int tid) {
    #pragma unroll
    for (int i = 0; i < TR/64; i++) {
        int c = tid + 256*i; int row = c >> 2, q = c & 3;
        *(uint4*)(dst + SWZ((uint32_t)(row * 64 + q * 16))) = r[i];
    }
}

// ---------------- warp-MMA NT GEMM: C[r,c] = sum_k A[r,k]*B[c,k] (+bias) ----
// MODE 0: A,B fp32 (split on the fly, 3 MMAs/product). MODE 1: presplit bf16.
// Block 128 x NT, BK=32, 8 warps (4 m x 2 n), double-buffered smem.
template<int NT, int MODE>
__global__ void __launch_bounds__(256) mma_gemm(
    const void* Ap, const void* Ap2, const void* Bp, const void* Bp2,
    const float* __restrict__ bias, float* __restrict__ C,
    int K, int lda, int ldb, int ldc,
    long aStrB, long aStrH, long bStrB, long bStrH, long cStrB, long cStrH,
    float ascale)
{
    extern __shared__ char sm[];
    constexpr int WARP_N = NT / 2;
    constexpr int N8T    = WARP_N / 8;
    constexpr int STAGE  = 16384 + NT * 128;  // Ahi+Alo (16K) + Bhi+Blo

    int tid = threadIdx.x, wid = tid >> 5, lane = tid & 31;
    int wm = wid & 3, wn = wid >> 2;
    int z = blockIdx.z;
    long za = (long)(z >> 4) * aStrB + (long)(z & 15) * aStrH;
    long zb = (long)(z >> 4) * bStrB + (long)(z & 15) * bStrH;
    long zc = (long)(z >> 4) * cStrB + (long)(z & 15) * cStrH;
    long row0 = (long)blockIdx.y * 128;
    int  col0 = blockIdx.x * NT;

    const float* A32 = nullptr; const float* B32 = nullptr;
    const __nv_bfloat16 *A16h = nullptr, *A16l = nullptr,
                        *B16h = nullptr, *B16l = nullptr;
    if (MODE == 0) {
        A32 = (const float*)Ap + za + row0 * lda;
        B32 = (const float*)Bp + zb + (long)col0 * ldb;
    } else {
        A16h = (const __nv_bfloat16*)Ap  + za + row0 * lda;
        A16l = (const __nv_bfloat16*)Ap2 + za + row0 * lda;
        B16h = (const __nv_bfloat16*)Bp  + zb + (long)col0 * ldb;
        B16l = (const __nv_bfloat16*)Bp2 + zb + (long)col0 * ldb;
    }

    float acc[2][N8T][4];
    #pragma unroll
    for (int mt = 0; mt < 2; mt++)
        #pragma unroll
        for (int nt = 0; nt < N8T; nt++)
            #pragma unroll
            for (int j = 0; j < 4; j++) acc[mt][nt][j] = 0.f;

    float4 ra[4], rb[4];
    uint4 sah[2], sal[2], sbh[NT/64 > 0 ? NT/64 : 1], sbl[NT/64 > 0 ? NT/64 : 1];

    const int nCh = K >> 5;
    if (MODE == 0) {
        ldg_f32<128>(A32, lda, 0, ra, tid);
        ldg_f32<NT>(B32, ldb, 0, rb, tid);
    } else {
        ldg_bf16<128>(A16h, lda, 0, sah, tid);
        ldg_bf16<128>(A16l, lda, 0, sal, tid);
        ldg_bf16<NT>(B16h, ldb, 0, sbh, tid);
        ldg_bf16<NT>(B16l, ldb, 0, sbl, tid);
    }

    for (int c = 0; c < nCh; c++) {
        char* bufAh = sm + (c & 1) * STAGE;
        char* bufAl = bufAh + 8192;
        char* bufBh = bufAh + 16384;
        char* bufBl = bufBh + NT * 64;
        if (MODE == 0) {
            sts_split<128>(bufAh, bufAl, ra, ascale, tid);
            sts_split<NT>(bufBh, bufBl, rb, 1.f, tid);
            if (c + 1 < nCh) {
                ldg_f32<128>(A32, lda, (c+1)*32, ra, tid);
                ldg_f32<NT>(B32, ldb, (c+1)*32, rb, tid);
            }
        } else {
            sts_bf16<128>(bufAh, sah, tid);
            sts_bf16<128>(bufAl, sal, tid);
            sts_bf16<NT>(bufBh, sbh, tid);
            sts_bf16<NT>(bufBl, sbl, tid);
            if (c + 1 < nCh) {
                ldg_bf16<128>(A16h, lda, (c+1)*32, sah, tid);
                ldg_bf16<128>(A16l, lda, (c+1)*32, sal, tid);
                ldg_bf16<NT>(B16h, ldb, (c+1)*32, sbh, tid);
                ldg_bf16<NT>(B16l, ldb, (c+1)*32, sbl, tid);
            }
        }
        __syncthreads();

        uint32_t baseAh = smem_u32(bufAh);
        uint32_t baseAl = baseAh + 8192;
        uint32_t baseBh = baseAh + 16384;
        uint32_t baseBl = baseBh + NT * 64;
        int r = lane & 7, t = lane >> 3;

        #pragma unroll
        for (int ks = 0; ks < 2; ks++) {
            int kb = ks * 32;   // byte offset of k16 step
            uint32_t bh[2*N8T], bl[2*N8T];
            #pragma unroll
            for (int p = 0; p < N8T/2; p++) {
                int brow = wn * WARP_N + p * 16 + ((t >> 1) << 3) + r;
                int bcol = kb + ((t & 1) << 4);
                uint32_t o = SWZ((uint32_t)(brow * 64 + bcol));
                ldm_x4(&bh[p*4], baseBh + o);
                ldm_x4(&bl[p*4], baseBl + o);
            }
            #pragma unroll
            for (int mt = 0; mt < 2; mt++) {
                int arow = wm * 32 + mt * 16 + ((t & 1) << 3) + r;
                int acol = kb + ((t >> 1) << 4);
                uint32_t o = SWZ((uint32_t)(arow * 64 + acol));
                uint32_t ah4[4], al4[4];
                ldm_x4(ah4, baseAh + o);
                ldm_x4(al4, baseAl + o);
                #pragma unroll
                for (int nt = 0; nt < N8T; nt++) {
                    mma16816(acc[mt][nt], ah4, &bh[nt*2]);
                    mma16816(acc[mt][nt], ah4, &bl[nt*2]);
                    mma16816(acc[mt][nt], al4, &bh[nt*2]);
                }
            }
        }
        // single barrier per chunk: next STS targets the other buffer
    }

    // epilogue: fragment-direct stores (+bias)
    long crow = row0 + wm * 32 + (lane >> 2);
    #pragma unroll
    for (int mt = 0; mt < 2; mt++) {
        #pragma unroll
        for (int nt = 0; nt < N8T; nt++) {
            int cc = col0 + wn * WARP_N + nt * 8 + ((lane & 3) << 1);
            float b0 = 0.f, b1 = 0.f;
            if (bias) { b0 = bias[cc]; b1 = bias[cc + 1]; }
            long rr = crow + mt * 16;
            float2 v0 = make_float2(acc[mt][nt][0] + b0, acc[mt][nt][1] + b1);
            float2 v1 = make_float2(acc[mt][nt][2] + b0, acc[mt][nt][3] + b1);
            *(float2*)(C + zc + rr * (long)ldc + cc) = v0;
            *(float2*)(C + zc + (rr + 8) * (long)ldc + cc) = v1;
        }
    }
}

// ---------------- softmax over M=512, fp32 in, split bf16 out --------------
__global__ void __launch_bounds__(256) softmax_kernel(
    const float* __restrict__ S, __nv_bfloat16* __restrict__ Phi,
    __nv_bfloat16* __restrict__ Plo)
{
    long row = (long)blockIdx.x * 8 + (threadIdx.x >> 5);
    int lane = threadIdx.x & 31;
    const float* sr = S + row * Mc;
    float v[16];
    float mx = -1e30f;
    #pragma unroll
    for (int j = 0; j < 4; j++) {
        float4 x = *(const float4*)(sr + j * 128 + lane * 4);
        v[4*j] = x.x; v[4*j+1] = x.y; v[4*j+2] = x.z; v[4*j+3] = x.w;
        mx = fmaxf(mx, fmaxf(fmaxf(x.x, x.y), fmaxf(x.z, x.w)));
    }
    #pragma unroll
    for (int o = 16; o; o >>= 1) mx = fmaxf(mx, __shfl_xor_sync(0xffffffffu, mx, o));
    float sm = 0.f;
    #pragma unroll
    for (int i = 0; i < 16; i++) { v[i] = __expf(v[i] - mx); sm += v[i]; }
    #pragma unroll
    for (int o = 16; o; o >>= 1) sm += __shfl_xor_sync(0xffffffffu, sm, o);
    float inv = 1.f / sm;
    #pragma unroll
    for (int j = 0; j < 4; j++) {
        uint32_t h[2], l[2];
        #pragma unroll
        for (int q = 0; q < 2; q++)
            h[q] = pack_split(v[4*j+2*q] * inv, v[4*j+2*q+1] * inv, l[q]);
        *(uint2*)(Phi + row * Mc + j * 128 + lane * 4) = make_uint2(h[0], h[1]);
        *(uint2*)(Plo + row * Mc + j * 128 + lane * 4) = make_uint2(l[0], l[1]);
    }
}

// ---------------- V transpose: (M,E) fp32 -> per-head (D,M) split bf16 -----
__global__ void vtrans_kernel(const float* __restrict__ V,
                              __nv_bfloat16* __restrict__ hi,
                              __nv_bfloat16* __restrict__ lo)
{
    __shared__ float t[32][33];
    int m0 = blockIdx.x * 32;
    int h  = blockIdx.y;
    int tx = threadIdx.x, ty = threadIdx.y;  // (32,8)
    for (int d0 = 0; d0 < 64; d0 += 32) {
        for (int r = ty; r < 32; r += 8)
            t[r][tx] = V[(long)(m0 + r) * Ec + h * 64 + d0 + tx];
        __syncthreads();
        for (int r = ty; r < 32; r += 8) {
            float x = t[tx][r];
            __nv_bfloat16 xh = __float2bfloat16(x);
            long o = (long)h * Dc * Mc + (long)(d0 + r) * Mc + m0 + tx;
            hi[o] = xh;
            lo[o] = __float2bfloat16(x - __bfloat162float(xh));
        }
        __syncthreads();
    }
}

// ---------------- residual + LayerNorm -------------------------------------
__global__ void __launch_bounds__(256) resid_ln_kernel(
    const float* __restrict__ Pr, const float* __restrict__ Res,
    const float* __restrict__ gw, const float* __restrict__ bw,
    float* __restrict__ out)
{
    __shared__ float sA[8], sB[8];
    long row = blockIdx.x;
    int t = threadIdx.x;
    long base = row * Ec + t * 4;
    float4 p = *(const float4*)(Pr + base);
    float4 r = *(const float4*)(Res + base);
    float v0 = p.x+r.x, v1 = p.y+r.y, v2 = p.z+r.z, v3 = p.w+r.w;
    float s  = v0+v1+v2+v3;
    float sq = v0*v0+v1*v1+v2*v2+v3*v3;
    int lane = t & 31, wid = t >> 5;
    #pragma unroll
    for (int o = 16; o; o >>= 1) {
        s  += __shfl_xor_sync(0xffffffffu, s,  o);
        sq += __shfl_xor_sync(0xffffffffu, sq, o);
    }
    if (lane == 0) { sA[wid] = s; sB[wid] = sq; }
    __syncthreads();
    if (t < 32) {
        s  = (t < 8) ? sA[t] : 0.f;
        sq = (t < 8) ? sB[t] : 0.f;
        #pragma unroll
        for (int o = 4; o; o >>= 1) {
            s  += __shfl_xor_sync(0xffffffffu, s,  o);
            sq += __shfl_xor_sync(0xffffffffu, sq, o);
        }
        if (t == 0) { sA[0] = s; sB[0] = sq; }
    }
    __syncthreads();
    float mu  = sA[0] * (1.f/Ec);
    float var = sB[0] * (1.f/Ec) - mu*mu;
    float rs  = rsqrtf(var + 1e-5f);
    float4 g4 = *(const float4*)(gw + t*4);
    float4 b4 = *(const float4*)(bw + t*4);
    float4 o4;
    o4.x = (v0-mu)*rs*g4.x + b4.x;
    o4.y = (v1-mu)*rs*g4.y + b4.y;
    o4.z = (v2-mu)*rs*g4.z + b4.z;
    o4.w = (v3-mu)*rs*g4.w + b4.w;
    *(float4*)(out + base) = o4;
}

// ---------------- gate + blend + LayerNorm ---------------------------------
__global__ void __launch_bounds__(256) newmem_ln_kernel(
    const float* __restrict__ gmem, const float* __restrict__ gupd,
    const float* __restrict__ updv, const float* __restrict__ mem,
    const float* __restrict__ gw, const float* __restrict__ bw,
    float* __restrict__ out)
{
    __shared__ float sA[8], sB[8];
    int rb = blockIdx.x;
    int b  = rb >> 9;
    int m  = rb & 511;
    int t  = threadIdx.x;
    int e  = t * 4;
    float4 gm = *(const float4*)(gmem + (long)m*Ec + e);
    float4 gu = *(const float4*)(gupd + (long)b*Ec + e);
    float4 uu = *(const float4*)(updv + (long)b*Ec + e);
    float4 mm = *(const float4*)(mem  + (long)m*Ec + e);
    float g0 = 1.f/(1.f + __expf(-(gm.x + gu.x)));
    float g1 = 1.f/(1.f + __expf(-(gm.y + gu.y)));
    float g2 = 1.f/(1.f + __expf(-(gm.z + gu.z)));
    float g3 = 1.f/(1.f + __expf(-(gm.w + gu.w)));
    float v0 = g0*uu.x + (1.f-g0)*mm.x;
    float v1 = g1*uu.y + (1.f-g1)*mm.y;
    float v2 = g2*uu.z + (1.f-g2)*mm.z;
    float v3 = g3*uu.w + (1.f-g3)*mm.w;
    float s  = v0+v1+v2+v3;
    float sq = v0*v0+v1*v1+v2*v2+v3*v3;
    int lane = t & 31, wid = t >> 5;
    #pragma unroll
    for (int o = 16; o; o >>= 1) {
        s  += __shfl_xor_sync(0xffffffffu, s,  o);
        sq += __shfl_xor_sync(0xffffffffu, sq, o);
    }
    if (lane == 0) { sA[wid] = s; sB[wid] = sq; }
    __syncthreads();
    if (t < 32) {
        s  = (t < 8) ? sA[t] : 0.f;
        sq = (t < 8) ? sB[t] : 0.f;
        #pragma unroll
        for (int o = 4; o; o >>= 1) {
            s  += __shfl_xor_sync(0xffffffffu, s,  o);
            sq += __shfl_xor_sync(0xffffffffu, sq, o);
        }
        if (t == 0) { sA[0] = s; sB[0] = sq; }
    }
    __syncthreads();
    float mu  = sA[0] * (1.f/Ec);
    float var = sB[0] * (1.f/Ec) - mu*mu;
    float rs  = rsqrtf(var + 1e-5f);
    float4 g4 = *(const float4*)(gw + e);
    float4 b4 = *(const float4*)(bw + e);
    float4 o4;
    o4.x = (v0-mu)*rs*g4.x + b4.x;
    o4.y = (v1-mu)*rs*g4.y + b4.y;
    o4.z = (v2-mu)*rs*g4.z + b4.z;
    o4.w = (v3-mu)*rs*g4.w + b4.w;
    *(float4*)(out + (long)rb*Ec + e) = o4;
}

// ---------------- wq = mean over S ------------------------------------------
__global__ void __launch_bounds__(256) wq_partial_kernel(
    const float* __restrict__ Q, float* __restrict__ part)
{
    int e = blockIdx.x * 256 + threadIdx.x;
    int b = blockIdx.y;
    int z = blockIdx.z;
    const float* p = Q + ((long)b*Sc + (long)z*256) * Ec + e;
    float s = 0.f;
    for (int i = 0; i < 256; i++) s += p[(long)i * Ec];
    part[((long)z*Bc + b)*Ec + e] = s;
}
__global__ void __launch_bounds__(256) wq_final_kernel(
    const float* __restrict__ part, float* __restrict__ wq)
{
    int e = blockIdx.x * 256 + threadIdx.x;
    int b = blockIdx.y;
    float s = 0.f;
    #pragma unroll
    for (int z = 0; z < 8; z++) s += part[((long)z*Bc + b)*Ec + e];
    wq[(long)b*Ec + e] = s * (1.f/Sc);
}

// ---------------- per-batch GEMV -------------------------------------------
__global__ void __launch_bounds__(256) gemv_nt_kernel(
    const float* __restrict__ x, const float* __restrict__ W, long ldw,
    const float* __restrict__ bias, float* __restrict__ y)
{
    int j = blockIdx.x * 256 + threadIdx.x;
    int b = blockIdx.y;
    const float* wr = W + (long)j * ldw;
    const float* xb = x + (long)b * Ec;
    float acc = bias ? bias[j] : 0.f;
    for (int k = 0; k < Ec; k += 4) {
        float4 w4 = *(const float4*)(wr + k);
        float4 x4 = *(const float4*)(xb + k);
        acc += x4.x*w4.x + x4.y*w4.y + x4.z*w4.z + x4.w*w4.w;
    }
    y[(long)b*Ec + j] = acc;
}

// ---------------- host launcher --------------------------------------------
extern "C" void kernel_launch(void* const* d_in, const int* in_sizes, int n_in,
                              void* d_out, int out_size)
{
    const float* query   = (const float*)d_in[0];
    const float* memory  = (const float*)d_in[1];
    const float* r_in_w  = (const float*)d_in[2];
    const float* r_in_b  = (const float*)d_in[3];
    const float* r_out_w = (const float*)d_in[4];
    const float* r_out_b = (const float*)d_in[5];
    const float* w_in_w  = (const float*)d_in[6];
    const float* w_in_b  = (const float*)d_in[7];
    const float* w_out_w = (const float*)d_in[8];
    const float* w_out_b = (const float*)d_in[9];
    const float* rn_g    = (const float*)d_in[10];
    const float* rn_b    = (const float*)d_in[11];
    const float* wn_g    = (const float*)d_in[12];
    const float* wn_b    = (const float*)d_in[13];
    const float* gate_w  = (const float*)d_in[14];
    const float* gate_b  = (const float*)d_in[15];
    float* out = (float*)d_out;

    constexpr int SMEM128 = 2 * (16384 + 128 * 128);  // 65536
    constexpr int SMEM64  = 2 * (16384 + 64 * 128);   // 49152

    static float *pQ = nullptr, *pA, *pP, *pK, *pV, *pG, *pS,
                 *pWP, *pWQ, *pVW, *pUP, *pGU;
    static __nv_bfloat16 *pPhi, *pPlo, *pVthi, *pVtlo;
    if (!pQ) {
        cudaGetSymbolAddress((void**)&pA,   g_attn);
        cudaGetSymbolAddress((void**)&pP,   g_proj);
        cudaGetSymbolAddress((void**)&pK,   g_Kp);
        cudaGetSymbolAddress((void**)&pV,   g_Vp);
        cudaGetSymbolAddress((void**)&pG,   g_gmem);
        cudaGetSymbolAddress((void**)&pS,   g_scores);
        cudaGetSymbolAddress((void**)&pPhi, g_Phi);
        cudaGetSymbolAddress((void**)&pPlo, g_Plo);
        cudaGetSymbolAddress((void**)&pVthi,g_Vthi);
        cudaGetSymbolAddress((void**)&pVtlo,g_Vtlo);
        cudaGetSymbolAddress((void**)&pWP,  g_wqpart);
        cudaGetSymbolAddress((void**)&pWQ,  g_wq);
        cudaGetSymbolAddress((void**)&pVW,  g_vw);
        cudaGetSymbolAddress((void**)&pUP,  g_upd);
        cudaGetSymbolAddress((void**)&pGU,  g_gupd);
        cudaFuncSetAttribute(mma_gemm<128,0>,
            cudaFuncAttributeMaxDynamicSharedMemorySize, SMEM128);
        cudaFuncSetAttribute(mma_gemm<64,1>,
            cudaFuncAttributeMaxDynamicSharedMemorySize, SMEM64);
        cudaGetSymbolAddress((void**)&pQ,   g_Qp);   // last: guards init
    }

    // --- projections + gate (split-bf16 tensor cores) ---
    mma_gemm<128,0><<<dim3(8,128,1), 256, SMEM128>>>(
        query, nullptr, r_in_w, nullptr, r_in_b, pQ,
        Ec, Ec, Ec, Ec, 0,0,0,0,0,0, 1.f);
    mma_gemm<128,0><<<dim3(8,4,1), 256, SMEM128>>>(
        memory, nullptr, r_in_w + (size_t)Ec*Ec, nullptr, r_in_b + Ec, pK,
        Ec, Ec, Ec, Ec, 0,0,0,0,0,0, 1.f);
    mma_gemm<128,0><<<dim3(8,4,1), 256, SMEM128>>>(
        memory, nullptr, r_in_w + (size_t)2*Ec*Ec, nullptr, r_in_b + 2*Ec, pV,
        Ec, Ec, Ec, Ec, 0,0,0,0,0,0, 1.f);
    mma_gemm<128,0><<<dim3(8,4,1), 256, SMEM128>>>(
        memory, nullptr, gate_w, nullptr, gate_b, pG,
        Ec, Ec, 2*Ec, Ec, 0,0,0,0,0,0, 1.f);

    // --- attention: scores -> softmax(split P) -> P@V^T ---
    vtrans_kernel<<<dim3(Mc/32, Hc), dim3(32,8)>>>(pV, pVthi, pVtlo);
    mma_gemm<128,0><<<dim3(4,16,ZNc), 256, SMEM128>>>(
        pQ, nullptr, pK, nullptr, nullptr, pS,
        Dc, Ec, Ec, Mc,
        (long)Sc*Ec, 64, 0, 64, (long)Hc*Sc*Mc, (long)Sc*Mc, 0.125f);
    softmax_kernel<<<(ZNc*Sc)/8, 256>>>(pS, pPhi, pPlo);
    mma_gemm<64,1><<<dim3(1,16,ZNc), 256, SMEM64>>>(
        pPhi, pPlo, pVthi, pVtlo, nullptr, pA,
        Mc, Mc, Mc, Ec,
        (long)Hc*Sc*Mc, (long)Sc*Mc, 0, (long)Dc*Mc, (long)Sc*Ec, 64, 1.f);

    // --- out-proj + residual LN -> mem_out ---
    mma_gemm<128,0><<<dim3(8,128,1), 256, SMEM128>>>(
        pA, nullptr, r_out_w, nullptr, r_out_b, pP,
        Ec, Ec, Ec, Ec, 0,0,0,0,0,0, 1.f);
    resid_ln_kernel<<<Bc*Sc, 256>>>(pP, query, rn_g, rn_b, out);

    // --- write path (softmax over length-1 keys == 1) ---
    wq_partial_kernel<<<dim3(Ec/256, Bc, 8), 256>>>(query, pWP);
    wq_final_kernel  <<<dim3(Ec/256, Bc),    256>>>(pWP, pWQ);
    gemv_nt_kernel<<<dim3(Ec/256, Bc), 256>>>(pWQ, w_in_w + (size_t)2*Ec*Ec, Ec,   w_in_b + 2*Ec, pVW);
    gemv_nt_kernel<<<dim3(Ec/256, Bc), 256>>>(pVW, w_out_w,                  Ec,   w_out_b,       pUP);
    gemv_nt_kernel<<<dim3(Ec/256, Bc), 256>>>(pUP, gate_w + Ec,              2*Ec, nullptr,       pGU);
    newmem_ln_kernel<<<Bc*Mc, 256>>>(pG, pGU, pUP, memory, wn_g, wn_b,
                                     out + (size_t)Bc*Sc*Ec);
}

// round 7
// speedup vs baseline: 5.5791x; 1.5496x over previous
#include <cuda_runtime.h>
#include <cuda_fp16.h>
#include <cstdint>

#define Bc 8
#define Sc 2048
#define Mc 512
#define Ec 1024
#define Hc 16
#define Dc 64
#define ZNc (Bc*Hc)

__device__ float g_Qp  [(size_t)Bc*Sc*Ec];
__device__ float g_attn[(size_t)Bc*Sc*Ec];
__device__ float g_proj[(size_t)Bc*Sc*Ec];
__device__ float g_Kp  [Mc*Ec];
__device__ float g_Vp  [Mc*Ec];
__device__ float g_gmem[Mc*Ec];
__device__ __half g_Vt [Hc*Dc*Mc];
__device__ float g_wqpart[8*Bc*Ec];
__device__ float g_wq  [Bc*Ec];
__device__ float g_vw  [Bc*Ec];
__device__ float g_upd [Bc*Ec];
__device__ float g_gupd[Bc*Ec];

__device__ __forceinline__ uint32_t smem_u32(const void* p) {
    uint32_t a;
    asm("{ .reg .u64 t; cvta.to.shared.u64 t, %1; cvt.u32.u64 %0, t; }"
        : "=r"(a) : "l"(p));
    return a;
}
#define SWZ(off) ((off) ^ (((off) >> 3) & 0x30))

__device__ __forceinline__ void ldm_x4(uint32_t* r, uint32_t addr) {
    asm volatile("ldmatrix.sync.aligned.m8n8.x4.shared.b16 {%0,%1,%2,%3}, [%4];"
        : "=r"(r[0]), "=r"(r[1]), "=r"(r[2]), "=r"(r[3]) : "r"(addr));
}
__device__ __forceinline__ void mma_h(float* d, const uint32_t* a,
                                      const uint32_t* b) {
    asm volatile(
        "mma.sync.aligned.m16n8k16.row.col.f32.f16.f16.f32 "
        "{%0,%1,%2,%3}, {%4,%5,%6,%7}, {%8,%9}, {%0,%1,%2,%3};"
        : "+f"(d[0]), "+f"(d[1]), "+f"(d[2]), "+f"(d[3])
        : "r"(a[0]), "r"(a[1]), "r"(a[2]), "r"(a[3]), "r"(b[0]), "r"(b[1]));
}
__device__ __forceinline__ uint32_t f2h2(float a, float b) {
    __half2 h = __floats2half2_rn(a, b);
    return *reinterpret_cast<uint32_t*>(&h);
}

// 128 rows x 64 k fp32 tile: row = tid>>1, half = tid&1 (32-col half)
__device__ __forceinline__ void ldg64(const float* __restrict__ src, int ld,
                                      int k0, float4* r, int tid) {
    const float* p = src + (long)(tid >> 1) * ld + k0 + (tid & 1) * 32;
    #pragma unroll
    for (int i = 0; i < 8; i++) r[i] = *(const float4*)(p + i * 4);
}
// dst: two 8KB k-sub-chunks (32 k each), 64B swizzled rows, fp16
__device__ __forceinline__ void sts64h(char* dst, const float4* r, float sc,
                                       int tid) {
    int row = tid >> 1;
    char* base = dst + (tid & 1) * 8192;
    #pragma unroll
    for (int q = 0; q < 4; q++) {
        float4 x0 = r[2*q], x1 = r[2*q+1];
        uint4 u;
        u.x = f2h2(x0.x * sc, x0.y * sc);
        u.y = f2h2(x0.z * sc, x0.w * sc);
        u.z = f2h2(x1.x * sc, x1.y * sc);
        u.w = f2h2(x1.z * sc, x1.w * sc);
        *(uint4*)(base + SWZ((uint32_t)(row * 64 + q * 16))) = u;
    }
}

// ---------------- fp16 NT GEMM body: 128x128 tile, KC=64, 8 warps ----------
__device__ __forceinline__ void hgemm_body(
    const float* __restrict__ A, const float* __restrict__ Bw,
    const float* __restrict__ bias, float* __restrict__ C,
    int K, int lda, int ldb, int ldc, int col0, char* sm)
{
    int tid = threadIdx.x, wid = tid >> 5, lane = tid & 31;
    int wm = wid & 3, wn = wid >> 2;
    const float* Bcol = Bw + (long)col0 * ldb;

    float acc[2][8][4];
    #pragma unroll
    for (int mt = 0; mt < 2; mt++)
        #pragma unroll
        for (int nt = 0; nt < 8; nt++)
            #pragma unroll
            for (int j = 0; j < 4; j++) acc[mt][nt][j] = 0.f;

    float4 ra[8], rb[8];
    const int nCh = K >> 6;
    ldg64(A, lda, 0, ra, tid);
    ldg64(Bcol, ldb, 0, rb, tid);

    int r = lane & 7, t = lane >> 3;
    for (int c = 0; c < nCh; c++) {
        char* buf = sm + (c & 1) * 32768;
        sts64h(buf, ra, 1.f, tid);
        sts64h(buf + 16384, rb, 1.f, tid);
        if (c + 1 < nCh) {
            ldg64(A, lda, (c+1)*64, ra, tid);
            ldg64(Bcol, ldb, (c+1)*64, rb, tid);
        }
        __syncthreads();
        uint32_t aB = smem_u32(buf), bB = aB + 16384;
        #pragma unroll
        for (int ks = 0; ks < 4; ks++) {
            uint32_t sub = (uint32_t)(ks >> 1) * 8192, kb = (ks & 1) * 32;
            uint32_t bf[16];
            #pragma unroll
            for (int p = 0; p < 4; p++) {
                int brow = wn * 64 + p * 16 + ((t >> 1) << 3) + r;
                ldm_x4(&bf[p*4], bB + sub + SWZ((uint32_t)(brow*64 + kb + ((t&1)<<4))));
            }
            #pragma unroll
            for (int mt = 0; mt < 2; mt++) {
                int arow = wm * 32 + mt * 16 + ((t & 1) << 3) + r;
                uint32_t af[4];
                ldm_x4(af, aB + sub + SWZ((uint32_t)(arow*64 + kb + ((t>>1)<<4))));
                #pragma unroll
                for (int nt = 0; nt < 8; nt++)
                    mma_h(acc[mt][nt], af, &bf[nt*2]);
            }
        }
    }

    long crow = wm * 32 + (lane >> 2);
    #pragma unroll
    for (int mt = 0; mt < 2; mt++) {
        #pragma unroll
        for (int nt = 0; nt < 8; nt++) {
            int cc = col0 + wn * 64 + nt * 8 + ((lane & 3) << 1);
            float b0 = bias ? bias[cc] : 0.f;
            float b1 = bias ? bias[cc + 1] : 0.f;
            long rr2 = crow + mt * 16;
            *(float2*)(C + rr2 * (long)ldc + cc) =
                make_float2(acc[mt][nt][0] + b0, acc[mt][nt][1] + b1);
            *(float2*)(C + (rr2 + 8) * (long)ldc + cc) =
                make_float2(acc[mt][nt][2] + b0, acc[mt][nt][3] + b1);
        }
    }
}

__global__ void __launch_bounds__(256) hgemm_kernel(
    const float* A, const float* B, const float* bias, float* C,
    int K, int lda, int ldb, int ldc)
{
    extern __shared__ char sm[];
    hgemm_body(A + (long)blockIdx.y * 128 * lda, B, bias,
               C + (long)blockIdx.y * 128 * ldc,
               K, lda, ldb, ldc, blockIdx.x * 128, sm);
}

// merged Q/K/V/gate projections
__global__ void __launch_bounds__(256) proj4_kernel(
    const float* __restrict__ query, const float* __restrict__ memory,
    const float* __restrict__ r_in_w, const float* __restrict__ r_in_b,
    const float* __restrict__ gate_w, const float* __restrict__ gate_b,
    float* Qp, float* Kp, float* Vp, float* Gp)
{
    extern __shared__ char sm[];
    int y = blockIdx.y;
    const float *A, *B, *bias;
    float* C;
    int ldb = Ec;
    long row0;
    if (y < 128) {
        A = query; row0 = (long)y * 128;
        B = r_in_w; bias = r_in_b; C = Qp;
    } else {
        int s = y - 128;
        A = memory; row0 = (long)(s & 3) * 128;
        if (s < 4)      { B = r_in_w + (size_t)Ec*Ec;   bias = r_in_b + Ec;   C = Kp; }
        else if (s < 8) { B = r_in_w + (size_t)2*Ec*Ec; bias = r_in_b + 2*Ec; C = Vp; }
        else            { B = gate_w; bias = gate_b; C = Gp; ldb = 2*Ec; }
    }
    hgemm_body(A + row0 * Ec, B, bias, C + row0 * Ec,
               Ec, Ec, ldb, Ec, blockIdx.x * 128, sm);
}

// ---------------- fused flash attention ------------------------------------
// grid (16 q-tiles, ZNc); 8 warps x 16 q-rows; 4 key chunks of 128.
// smem: Q fp16 @0 (16K), K @16384 (16K), V^T @32768 (16K).
__global__ void __launch_bounds__(256) flash_kernel(
    const float* __restrict__ Qp, const float* __restrict__ Kp,
    const __half* __restrict__ Vt, float* __restrict__ O)
{
    extern __shared__ char sm[];
    int tid = threadIdx.x, wid = tid >> 5, lane = tid & 31;
    int zh = blockIdx.y, b = zh >> 4, h = zh & 15;
    long q0 = (long)blockIdx.x * 128;
    int r = lane & 7, t = lane >> 3;

    {
        float4 rq[8];
        ldg64(Qp + ((long)b * Sc + q0) * Ec + h * 64, Ec, 0, rq, tid);
        sts64h(sm, rq, 0.125f, tid);
    }

    float acc_o[8][4];
    #pragma unroll
    for (int nt = 0; nt < 8; nt++)
        #pragma unroll
        for (int j = 0; j < 4; j++) acc_o[nt][j] = 0.f;
    float m_run[2] = {-1e30f, -1e30f}, l_run[2] = {0.f, 0.f};

    const float* Ksrc = Kp + h * 64;
    const __half* Vsrc = Vt + (size_t)h * Dc * Mc;
    uint32_t smQ = smem_u32(sm), smK = smQ + 16384, smV = smQ + 32768;

    for (int c = 0; c < 4; c++) {
        float4 rk[8];
        ldg64(Ksrc + (long)c * 128 * Ec, Ec, 0, rk, tid);
        int vrow = tid >> 2, vq = tid & 3;
        const __half* vp = Vsrc + (long)vrow * Mc + c * 128 + vq * 32;
        uint4 v0 = *(const uint4*)vp;
        uint4 v1 = *(const uint4*)(vp + 8);
        uint4 v2 = *(const uint4*)(vp + 16);
        uint4 v3 = *(const uint4*)(vp + 24);
        __syncthreads();
        sts64h(sm + 16384, rk, 1.f, tid);
        {
            char* vb = sm + 32768 + vq * 4096;
            *(uint4*)(vb + SWZ((uint32_t)(vrow * 64 +  0))) = v0;
            *(uint4*)(vb + SWZ((uint32_t)(vrow * 64 + 16))) = v1;
            *(uint4*)(vb + SWZ((uint32_t)(vrow * 64 + 32))) = v2;
            *(uint4*)(vb + SWZ((uint32_t)(vrow * 64 + 48))) = v3;
        }
        __syncthreads();

        // scores S[16 x 128] per warp
        float acc_s[16][4];
        #pragma unroll
        for (int nt = 0; nt < 16; nt++)
            #pragma unroll
            for (int j = 0; j < 4; j++) acc_s[nt][j] = 0.f;
        #pragma unroll
        for (int ks = 0; ks < 4; ks++) {
            uint32_t sub = (uint32_t)(ks >> 1) * 8192, kb = (ks & 1) * 32;
            uint32_t af[4];
            int arow = wid * 16 + ((t & 1) << 3) + r;
            ldm_x4(af, smQ + sub + SWZ((uint32_t)(arow*64 + kb + ((t>>1)<<4))));
            uint32_t bf[32];
            #pragma unroll
            for (int p = 0; p < 8; p++) {
                int brow = p * 16 + ((t >> 1) << 3) + r;
                ldm_x4(&bf[p*4], smK + sub + SWZ((uint32_t)(brow*64 + kb + ((t&1)<<4))));
            }
            #pragma unroll
            for (int nt = 0; nt < 16; nt++)
                mma_h(acc_s[nt], af, &bf[nt*2]);
        }

        // online softmax: rows lane>>2 (sub 0) and +8 (sub 1)
        #pragma unroll
        for (int sub = 0; sub < 2; sub++) {
            float mx = -1e30f;
            #pragma unroll
            for (int nt = 0; nt < 16; nt++)
                mx = fmaxf(mx, fmaxf(acc_s[nt][sub*2], acc_s[nt][sub*2+1]));
            mx = fmaxf(mx, __shfl_xor_sync(0xffffffffu, mx, 1));
            mx = fmaxf(mx, __shfl_xor_sync(0xffffffffu, mx, 2));
            float mn = fmaxf(m_run[sub], mx);
            float scl = __expf(m_run[sub] - mn);
            float sum = 0.f;
            #pragma unroll
            for (int nt = 0; nt < 16; nt++) {
                float p0 = __expf(acc_s[nt][sub*2]   - mn);
                float p1 = __expf(acc_s[nt][sub*2+1] - mn);
                acc_s[nt][sub*2] = p0; acc_s[nt][sub*2+1] = p1;
                sum += p0 + p1;
            }
            sum += __shfl_xor_sync(0xffffffffu, sum, 1);
            sum += __shfl_xor_sync(0xffffffffu, sum, 2);
            l_run[sub] = l_run[sub] * scl + sum;
            m_run[sub] = mn;
            #pragma unroll
            for (int nt = 0; nt < 8; nt++) {
                acc_o[nt][sub*2]   *= scl;
                acc_o[nt][sub*2+1] *= scl;
            }
        }

        // PV: O += P @ V^T (P fragments from registers)
        #pragma unroll
        for (int s = 0; s < 8; s++) {
            uint32_t ah[4];
            ah[0] = f2h2(acc_s[2*s][0],   acc_s[2*s][1]);
            ah[1] = f2h2(acc_s[2*s][2],   acc_s[2*s][3]);
            ah[2] = f2h2(acc_s[2*s+1][0], acc_s[2*s+1][1]);
            ah[3] = f2h2(acc_s[2*s+1][2], acc_s[2*s+1][3]);
            uint32_t vsub = (uint32_t)(s >> 1) * 4096, vkb = (s & 1) * 32;
            uint32_t vf[16];
            #pragma unroll
            for (int p = 0; p < 4; p++) {
                int drow = p * 16 + ((t >> 1) << 3) + r;
                ldm_x4(&vf[p*4], smV + vsub + SWZ((uint32_t)(drow*64 + vkb + ((t&1)<<4))));
            }
            #pragma unroll
            for (int nt = 0; nt < 8; nt++)
                mma_h(acc_o[nt], ah, &vf[nt*2]);
        }
    }

    float inv0 = 1.f / l_run[0], inv1 = 1.f / l_run[1];
    long orow = (long)b * Sc + q0 + wid * 16 + (lane >> 2);
    float* dst = O + orow * Ec + h * 64 + (lane & 3) * 2;
    #pragma unroll
    for (int nt = 0; nt < 8; nt++) {
        *(float2*)(dst + nt*8) =
            make_float2(acc_o[nt][0] * inv0, acc_o[nt][1] * inv0);
        *(float2*)(dst + 8*Ec + nt*8) =
            make_float2(acc_o[nt][2] * inv1, acc_o[nt][3] * inv1);
    }
}

// ---------------- V transpose: (M,E) fp32 -> per-head (D,M) fp16 -----------
__global__ void vtrans_kernel(const float* __restrict__ V, __half* __restrict__ Vt)
{
    __shared__ float t[32][33];
    int m0 = blockIdx.x * 32;
    int h  = blockIdx.y;
    int tx = threadIdx.x, ty = threadIdx.y;
    for (int d0 = 0; d0 < 64; d0 += 32) {
        for (int r2 = ty; r2 < 32; r2 += 8)
            t[r2][tx] = V[(long)(m0 + r2) * Ec + h * 64 + d0 + tx];
        __syncthreads();
        for (int r2 = ty; r2 < 32; r2 += 8)
            Vt[(size_t)h * Dc * Mc + (long)(d0 + r2) * Mc + m0 + tx] =
                __float2half(t[tx][r2]);
        __syncthreads();
    }
}

// ---------------- residual + LayerNorm -------------------------------------
__global__ void __launch_bounds__(256) resid_ln_kernel(
    const float* __restrict__ Pr, const float* __restrict__ Res,
    const float* __restrict__ gw, const float* __restrict__ bw,
    float* __restrict__ out)
{
    __shared__ float sA[8], sB[8];
    long row = blockIdx.x;
    int tt = threadIdx.x;
    long base = row * Ec + tt * 4;
    float4 p = *(const float4*)(Pr + base);
    float4 rv = *(const float4*)(Res + base);
    float v0 = p.x+rv.x, v1 = p.y+rv.y, v2 = p.z+rv.z, v3 = p.w+rv.w;
    float s  = v0+v1+v2+v3;
    float sq = v0*v0+v1*v1+v2*v2+v3*v3;
    int lane = tt & 31, wd = tt >> 5;
    #pragma unroll
    for (int o = 16; o; o >>= 1) {
        s  += __shfl_xor_sync(0xffffffffu, s,  o);
        sq += __shfl_xor_sync(0xffffffffu, sq, o);
    }
    if (lane == 0) { sA[wd] = s; sB[wd] = sq; }
    __syncthreads();
    if (tt < 32) {
        s  = (tt < 8) ? sA[tt] : 0.f;
        sq = (tt < 8) ? sB[tt] : 0.f;
        #pragma unroll
        for (int o = 4; o; o >>= 1) {
            s  += __shfl_xor_sync(0xffffffffu, s,  o);
            sq += __shfl_xor_sync(0xffffffffu, sq, o);
        }
        if (tt == 0) { sA[0] = s; sB[0] = sq; }
    }
    __syncthreads();
    float mu  = sA[0] * (1.f/Ec);
    float var = sB[0] * (1.f/Ec) - mu*mu;
    float rs  = rsqrtf(var + 1e-5f);
    float4 g4 = *(const float4*)(gw + tt*4);
    float4 b4 = *(const float4*)(bw + tt*4);
    float4 o4;
    o4.x = (v0-mu)*rs*g4.x + b4.x;
    o4.y = (v1-mu)*rs*g4.y + b4.y;
    o4.z = (v2-mu)*rs*g4.z + b4.z;
    o4.w = (v3-mu)*rs*g4.w + b4.w;
    *(float4*)(out + base) = o4;
}

// ---------------- gate + blend + LayerNorm ---------------------------------
__global__ void __launch_bounds__(256) newmem_ln_kernel(
    const float* __restrict__ gmem, const float* __restrict__ gupd,
    const float* __restrict__ updv, const float* __restrict__ mem,
    const float* __restrict__ gw, const float* __restrict__ bw,
    float* __restrict__ out)
{
    __shared__ float sA[8], sB[8];
    int rb = blockIdx.x;
    int b  = rb >> 9;
    int m  = rb & 511;
    int tt = threadIdx.x;
    int e  = tt * 4;
    float4 gm = *(const float4*)(gmem + (long)m*Ec + e);
    float4 gu = *(const float4*)(gupd + (long)b*Ec + e);
    float4 uu = *(const float4*)(updv + (long)b*Ec + e);
    float4 mm = *(const float4*)(mem  + (long)m*Ec + e);
    float g0 = 1.f/(1.f + __expf(-(gm.x + gu.x)));
    float g1 = 1.f/(1.f + __expf(-(gm.y + gu.y)));
    float g2 = 1.f/(1.f + __expf(-(gm.z + gu.z)));
    float g3 = 1.f/(1.f + __expf(-(gm.w + gu.w)));
    float v0 = g0*uu.x + (1.f-g0)*mm.x;
    float v1 = g1*uu.y + (1.f-g1)*mm.y;
    float v2 = g2*uu.z + (1.f-g2)*mm.z;
    float v3 = g3*uu.w + (1.f-g3)*mm.w;
    float s  = v0+v1+v2+v3;
    float sq = v0*v0+v1*v1+v2*v2+v3*v3;
    int lane = tt & 31, wd = tt >> 5;
    #pragma unroll
    for (int o = 16; o; o >>= 1) {
        s  += __shfl_xor_sync(0xffffffffu, s,  o);
        sq += __shfl_xor_sync(0xffffffffu, sq, o);
    }
    if (lane == 0) { sA[wd] = s; sB[wd] = sq; }
    __syncthreads();
    if (tt < 32) {
        s  = (tt < 8) ? sA[tt] : 0.f;
        sq = (tt < 8) ? sB[tt] : 0.f;
        #pragma unroll
        for (int o = 4; o; o >>= 1) {
            s  += __shfl_xor_sync(0xffffffffu, s,  o);
            sq += __shfl_xor_sync(0xffffffffu, sq, o);
        }
        if (tt == 0) { sA[0] = s; sB[0] = sq; }
    }
    __syncthreads();
    float mu  = sA[0] * (1.f/Ec);
    float var = sB[0] * (1.f/Ec) - mu*mu;
    float rs  = rsqrtf(var + 1e-5f);
    float4 g4 = *(const float4*)(gw + e);
    float4 b4 = *(const float4*)(bw + e);
    float4 o4;
    o4.x = (v0-mu)*rs*g4.x + b4.x;
    o4.y = (v1-mu)*rs*g4.y + b4.y;
    o4.z = (v2-mu)*rs*g4.z + b4.z;
    o4.w = (v3-mu)*rs*g4.w + b4.w;
    *(float4*)(out + (long)rb*Ec + e) = o4;
}

// ---------------- wq = mean over S ------------------------------------------
__global__ void __launch_bounds__(256) wq_partial_kernel(
    const float* __restrict__ Q, float* __restrict__ part)
{
    int e = blockIdx.x * 256 + threadIdx.x;
    int b = blockIdx.y;
    int z = blockIdx.z;
    const float* p = Q + ((long)b*Sc + (long)z*256) * Ec + e;
    float s = 0.f;
    for (int i = 0; i < 256; i++) s += p[(long)i * Ec];
    part[((long)z*Bc + b)*Ec + e] = s;
}
__global__ void __launch_bounds__(256) wq_final_kernel(
    const float* __restrict__ part, float* __restrict__ wq)
{
    int e = blockIdx.x * 256 + threadIdx.x;
    int b = blockIdx.y;
    float s = 0.f;
    #pragma unroll
    for (int z = 0; z < 8; z++) s += part[((long)z*Bc + b)*Ec + e];
    wq[(long)b*Ec + e] = s * (1.f/Sc);
}

// ---------------- per-batch GEMV -------------------------------------------
__global__ void __launch_bounds__(256) gemv_nt_kernel(
    const float* __restrict__ x, const float* __restrict__ W, long ldw,
    const float* __restrict__ bias, float* __restrict__ y)
{
    int j = blockIdx.x * 256 + threadIdx.x;
    int b = blockIdx.y;
    const float* wr = W + (long)j * ldw;
    const float* xb = x + (long)b * Ec;
    float acc = bias ? bias[j] : 0.f;
    for (int k = 0; k < Ec; k += 4) {
        float4 w4 = *(const float4*)(wr + k);
        float4 x4 = *(const float4*)(xb + k);
        acc += x4.x*w4.x + x4.y*w4.y + x4.z*w4.z + x4.w*w4.w;
    }
    y[(long)b*Ec + j] = acc;
}

// ---------------- host launcher --------------------------------------------
extern "C" void kernel_launch(void* const* d_in, const int* in_sizes, int n_in,
                              void* d_out, int out_size)
{
    const float* query   = (const float*)d_in[0];
    const float* memory  = (const float*)d_in[1];
    const float* r_in_w  = (const float*)d_in[2];
    const float* r_in_b  = (const float*)d_in[3];
    const float* r_out_w = (const float*)d_in[4];
    const float* r_out_b = (const float*)d_in[5];
    const float* w_in_w  = (const float*)d_in[6];
    const float* w_in_b  = (const float*)d_in[7];
    const float* w_out_w = (const float*)d_in[8];
    const float* w_out_b = (const float*)d_in[9];
    const float* rn_g    = (const float*)d_in[10];
    const float* rn_b    = (const float*)d_in[11];
    const float* wn_g    = (const float*)d_in[12];
    const float* wn_b    = (const float*)d_in[13];
    const float* gate_w  = (const float*)d_in[14];
    const float* gate_b  = (const float*)d_in[15];
    float* out = (float*)d_out;

    constexpr int SMEM_G = 65536;   // hgemm double-buffered
    constexpr int SMEM_F = 49152;   // flash Q+K+V

    static float *pQ = nullptr, *pA, *pP, *pK, *pV, *pG,
                 *pWP, *pWQ, *pVW, *pUP, *pGU;
    static __half *pVt;
    if (!pQ) {
        cudaGetSymbolAddress((void**)&pA,   g_attn);
        cudaGetSymbolAddress((void**)&pP,   g_proj);
        cudaGetSymbolAddress((void**)&pK,   g_Kp);
        cudaGetSymbolAddress((void**)&pV,   g_Vp);
        cudaGetSymbolAddress((void**)&pG,   g_gmem);
        cudaGetSymbolAddress((void**)&pVt,  g_Vt);
        cudaGetSymbolAddress((void**)&pWP,  g_wqpart);
        cudaGetSymbolAddress((void**)&pWQ,  g_wq);
        cudaGetSymbolAddress((void**)&pVW,  g_vw);
        cudaGetSymbolAddress((void**)&pUP,  g_upd);
        cudaGetSymbolAddress((void**)&pGU,  g_gupd);
        cudaFuncSetAttribute(proj4_kernel,
            cudaFuncAttributeMaxDynamicSharedMemorySize, SMEM_G);
        cudaFuncSetAttribute(hgemm_kernel,
            cudaFuncAttributeMaxDynamicSharedMemorySize, SMEM_G);
        cudaFuncSetAttribute(flash_kernel,
            cudaFuncAttributeMaxDynamicSharedMemorySize, SMEM_F);
        cudaGetSymbolAddress((void**)&pQ,   g_Qp);   // last: guards init
    }

    // projections (Q/K/V/gate in one launch)
    proj4_kernel<<<dim3(8,140), 256, SMEM_G>>>(
        query, memory, r_in_w, r_in_b, gate_w, gate_b, pQ, pK, pV, pG);

    // attention
    vtrans_kernel<<<dim3(Mc/32, Hc), dim3(32,8)>>>(pV, pVt);
    flash_kernel<<<dim3(Sc/128, ZNc), 256, SMEM_F>>>(pQ, pK, pVt, pA);

    // out-proj + residual LN -> mem_out
    hgemm_kernel<<<dim3(8,128), 256, SMEM_G>>>(pA, r_out_w, r_out_b, pP,
                                               Ec, Ec, Ec, Ec);
    resid_ln_kernel<<<Bc*Sc, 256>>>(pP, query, rn_g, rn_b, out);

    // write path (softmax over length-1 keys == 1)
    wq_partial_kernel<<<dim3(Ec/256, Bc, 8), 256>>>(query, pWP);
    wq_final_kernel  <<<dim3(Ec/256, Bc),    256>>>(pWP, pWQ);
    gemv_nt_kernel<<<dim3(Ec/256, Bc), 256>>>(pWQ, w_in_w + (size_t)2*Ec*Ec, Ec,   w_in_b + 2*Ec, pVW);
    gemv_nt_kernel<<<dim3(Ec/256, Bc), 256>>>(pVW, w_out_w,                  Ec,   w_out_b,       pUP);
    gemv_nt_kernel<<<dim3(Ec/256, Bc), 256>>>(pUP, gate_w + Ec,              2*Ec, nullptr,       pGU);
    newmem_ln_kernel<<<Bc*Mc, 256>>>(pG, pGU, pUP, memory, wn_g, wn_b,
                                     out + (size_t)Bc*Sc*Ec);
}

// round 8
// speedup vs baseline: 6.5293x; 1.1703x over previous
#include <cuda_runtime.h>
#include <cuda_fp16.h>
#include <cstdint>

#define Bc 8
#define Sc 2048
#define Mc 512
#define Ec 1024
#define Hc 16
#define Dc 64
#define ZNc (Bc*Hc)

__device__ __half g_Qh  [(size_t)Bc*Sc*Ec];   // 32 MB (Q proj, pre-scaled 1/8)
__device__ __half g_Ah  [(size_t)Bc*Sc*Ec];   // 32 MB (attention out fp16)
__device__ float  g_proj[(size_t)Bc*Sc*Ec];   // 64 MB (out-proj fp32)
__device__ __half g_Kh  [Mc*Ec];
__device__ __half g_Vh  [Mc*Ec];
__device__ __half g_Vt  [Hc*Dc*Mc];
__device__ float  g_gmem[Mc*Ec];
__device__ float  g_wqpart[8*Bc*Ec];
__device__ float  g_wq  [Bc*Ec];
__device__ float  g_vw  [Bc*Ec];
__device__ float  g_upd [Bc*Ec];
__device__ float  g_gupd[Bc*Ec];

__device__ __forceinline__ uint32_t smem_u32(const void* p) {
    uint32_t a;
    asm("{ .reg .u64 t; cvta.to.shared.u64 t, %1; cvt.u32.u64 %0, t; }"
        : "=r"(a) : "l"(p));
    return a;
}
// SW128: 128B rows, 8-row atom, XOR byte bits (7,8,9) onto (4,5,6)
#define SWZ(off) ((off) ^ (((off) >> 3) & 0x70))

__device__ __forceinline__ void ldm_x4(uint32_t* r, uint32_t addr) {
    asm volatile("ldmatrix.sync.aligned.m8n8.x4.shared.b16 {%0,%1,%2,%3}, [%4];"
        : "=r"(r[0]), "=r"(r[1]), "=r"(r[2]), "=r"(r[3]) : "r"(addr));
}
__device__ __forceinline__ void mma_h(float* d, const uint32_t* a,
                                      const uint32_t* b) {
    asm volatile(
        "mma.sync.aligned.m16n8k16.row.col.f32.f16.f16.f32 "
        "{%0,%1,%2,%3}, {%4,%5,%6,%7}, {%8,%9}, {%0,%1,%2,%3};"
        : "+f"(d[0]), "+f"(d[1]), "+f"(d[2]), "+f"(d[3])
        : "r"(a[0]), "r"(a[1]), "r"(a[2]), "r"(a[3]), "r"(b[0]), "r"(b[1]));
}
__device__ __forceinline__ uint32_t f2h2(float a, float b) {
    __half2 h = __floats2half2_rn(a, b);
    return *reinterpret_cast<uint32_t*>(&h);
}

// ============ coalesced tile loaders (128 rows x 64 k), SW128 smem =========
// fp32 source: 8 rounds, lane-consecutive 16B within a row (256B fp32 rows)
__device__ __forceinline__ void ldgA32(const float* __restrict__ src, int ld,
                                       int k0, float4* r, int tid) {
    #pragma unroll
    for (int i = 0; i < 8; i++) {
        int s = i * 256 + tid, row = s >> 4, c4 = s & 15;
        r[i] = *(const float4*)(src + (long)row * ld + k0 + c4 * 4);
    }
}
__device__ __forceinline__ void stsA32(char* dst, const float4* r, int tid) {
    #pragma unroll
    for (int i = 0; i < 8; i++) {
        int s = i * 256 + tid, row = s >> 4, c4 = s & 15;
        uint2 u = make_uint2(f2h2(r[i].x, r[i].y), f2h2(r[i].z, r[i].w));
        *(uint2*)(dst + SWZ((uint32_t)(row * 128 + c4 * 8))) = u;
    }
}
// fp16 source: 4 rounds, direct uint4 copy (128B fp16 rows)
__device__ __forceinline__ void ldgA16(const __half* __restrict__ src, int ld,
                                       int k0, uint4* r, int tid) {
    #pragma unroll
    for (int i = 0; i < 4; i++) {
        int s = i * 256 + tid, row = s >> 3, c8 = s & 7;
        r[i] = *(const uint4*)(src + (long)row * ld + k0 + c8 * 8);
    }
}
__device__ __forceinline__ void stsA16(char* dst, const uint4* r, int tid) {
    #pragma unroll
    for (int i = 0; i < 4; i++) {
        int s = i * 256 + tid, row = s >> 3, c8 = s & 7;
        *(uint4*)(dst + SWZ((uint32_t)(row * 128 + c8 * 16))) = r[i];
    }
}

// ============ fp16 NT GEMM body: 128x128 tile, KC=64, 8 warps ==============
// AH: A is fp16 in gmem. outh: write C as fp16. cscale applied at epilogue.
template<int AH>
__device__ __forceinline__ void hgemm_body(
    const void* Ap, const float* __restrict__ Bw, const float* __restrict__ bias,
    void* Cp, int outh, float cscale,
    int K, int lda, int ldb, int ldc, int col0, char* sm)
{
    int tid = threadIdx.x, wid = tid >> 5, lane = tid & 31;
    int wm = wid & 3, wn = wid >> 2;
    const float* Bcol = Bw + (long)col0 * ldb;

    float acc[2][8][4];
    #pragma unroll
    for (int mt = 0; mt < 2; mt++)
        #pragma unroll
        for (int nt = 0; nt < 8; nt++)
            #pragma unroll
            for (int j = 0; j < 4; j++) acc[mt][nt][j] = 0.f;

    float4 raf[8], rb[8];
    uint4  rah[4];
    const int nCh = K >> 6;
    if (AH) ldgA16((const __half*)Ap, lda, 0, rah, tid);
    else    ldgA32((const float*)Ap, lda, 0, raf, tid);
    ldgA32(Bcol, ldb, 0, rb, tid);

    int r = lane & 7, t = lane >> 3;
    for (int c = 0; c < nCh; c++) {
        char* buf = sm + (c & 1) * 32768;
        if (AH) stsA16(buf, rah, tid);
        else    stsA32(buf, raf, tid);
        stsA32(buf + 16384, rb, tid);
        if (c + 1 < nCh) {
            if (AH) ldgA16((const __half*)Ap, lda, (c+1)*64, rah, tid);
            else    ldgA32((const float*)Ap, lda, (c+1)*64, raf, tid);
            ldgA32(Bcol, ldb, (c+1)*64, rb, tid);
        }
        __syncthreads();
        uint32_t aB = smem_u32(buf), bB = aB + 16384;
        #pragma unroll
        for (int ks = 0; ks < 4; ks++) {
            uint32_t kb = (uint32_t)ks * 32;
            uint32_t bf[16];
            #pragma unroll
            for (int p = 0; p < 4; p++) {
                int brow = wn * 64 + p * 16 + ((t >> 1) << 3) + r;
                ldm_x4(&bf[p*4], bB + SWZ((uint32_t)(brow*128 + kb + ((t&1)<<4))));
            }
            #pragma unroll
            for (int mt = 0; mt < 2; mt++) {
                int arow = wm * 32 + mt * 16 + ((t & 1) << 3) + r;
                uint32_t af[4];
                ldm_x4(af, aB + SWZ((uint32_t)(arow*128 + kb + ((t>>1)<<4))));
                #pragma unroll
                for (int nt = 0; nt < 8; nt++)
                    mma_h(acc[mt][nt], af, &bf[nt*2]);
            }
        }
    }

    long crow = wm * 32 + (lane >> 2);
    #pragma unroll
    for (int mt = 0; mt < 2; mt++) {
        #pragma unroll
        for (int nt = 0; nt < 8; nt++) {
            int cc = col0 + wn * 64 + nt * 8 + ((lane & 3) << 1);
            float b0 = bias ? bias[cc] : 0.f;
            float b1 = bias ? bias[cc + 1] : 0.f;
            long rr2 = crow + mt * 16;
            float v00 = (acc[mt][nt][0] + b0) * cscale;
            float v01 = (acc[mt][nt][1] + b1) * cscale;
            float v10 = (acc[mt][nt][2] + b0) * cscale;
            float v11 = (acc[mt][nt][3] + b1) * cscale;
            if (outh) {
                *(uint32_t*)((__half*)Cp + rr2 * (long)ldc + cc) = f2h2(v00, v01);
                *(uint32_t*)((__half*)Cp + (rr2 + 8) * (long)ldc + cc) = f2h2(v10, v11);
            } else {
                *(float2*)((float*)Cp + rr2 * (long)ldc + cc) = make_float2(v00, v01);
                *(float2*)((float*)Cp + (rr2 + 8) * (long)ldc + cc) = make_float2(v10, v11);
            }
        }
    }
}

// out-proj: A fp16 (attention output), C fp32
__global__ void __launch_bounds__(256) hgemm16_kernel(
    const __half* A, const float* B, const float* bias, float* C,
    int K, int lda, int ldb, int ldc)
{
    extern __shared__ char sm[];
    hgemm_body<1>(A + (long)blockIdx.y * 128 * lda, B, bias,
                  C + (long)blockIdx.y * 128 * ldc, 0, 1.f,
                  K, lda, ldb, ldc, blockIdx.x * 128, sm);
}

// merged Q/K/V/gate projections (A fp32); Q/K/V out fp16, gate out fp32
__global__ void __launch_bounds__(256) proj4_kernel(
    const float* __restrict__ query, const float* __restrict__ memory,
    const float* __restrict__ r_in_w, const float* __restrict__ r_in_b,
    const float* __restrict__ gate_w, const float* __restrict__ gate_b,
    __half* Qh, __half* Kh, __half* Vh, float* Gp)
{
    extern __shared__ char sm[];
    int y = blockIdx.y;
    const float *A, *B, *bias;
    void* C;
    int ldb = Ec, outh = 1;
    float cs = 1.f;
    long row0;
    if (y < 128) {
        A = query; row0 = (long)y * 128;
        B = r_in_w; bias = r_in_b; C = Qh; cs = 0.125f;
    } else {
        int s = y - 128;
        A = memory; row0 = (long)(s & 3) * 128;
        if (s < 4)      { B = r_in_w + (size_t)Ec*Ec;   bias = r_in_b + Ec;   C = Kh; }
        else if (s < 8) { B = r_in_w + (size_t)2*Ec*Ec; bias = r_in_b + 2*Ec; C = Vh; }
        else            { B = gate_w; bias = gate_b; C = Gp; outh = 0; ldb = 2*Ec; }
    }
    void* Coff = outh ? (void*)((__half*)C + row0 * Ec)
                      : (void*)((float*)C + row0 * Ec);
    hgemm_body<0>(A + row0 * Ec, B, bias, Coff, outh, cs,
                  Ec, Ec, ldb, Ec, blockIdx.x * 128, sm);
}

// ============ fused flash attention (fp16 Q/K/V, fp16 O) ===================
// grid (16 q-tiles, ZNc); 8 warps x 16 q-rows; 4 key chunks of 128.
// smem: Q @0 (16K), K @16384 (16K), V^T @32768 (two 8K m-halves).
__global__ void __launch_bounds__(256) flash_kernel(
    const __half* __restrict__ Qh, const __half* __restrict__ Kh,
    const __half* __restrict__ Vt, __half* __restrict__ O)
{
    extern __shared__ char sm[];
    int tid = threadIdx.x, wid = tid >> 5, lane = tid & 31;
    int zh = blockIdx.y, b = zh >> 4, h = zh & 15;
    long q0 = (long)blockIdx.x * 128;
    int r = lane & 7, t = lane >> 3;

    // Q tile copy (already scaled 1/8 in proj4)
    #pragma unroll
    for (int i = 0; i < 4; i++) {
        int s = i * 256 + tid, row = s >> 3, c8 = s & 7;
        uint4 v = *(const uint4*)(Qh + ((long)b * Sc + q0 + row) * Ec + h * 64 + c8 * 8);
        *(uint4*)(sm + SWZ((uint32_t)(row * 128 + c8 * 16))) = v;
    }

    float acc_o[8][4];
    #pragma unroll
    for (int nt = 0; nt < 8; nt++)
        #pragma unroll
        for (int j = 0; j < 4; j++) acc_o[nt][j] = 0.f;
    float m_run[2] = {-1e30f, -1e30f}, l_run[2] = {0.f, 0.f};

    uint32_t smQ = smem_u32(sm), smK = smQ + 16384, smV = smQ + 32768;

    for (int c = 0; c < 4; c++) {
        uint4 kreg[4], vreg[4];
        #pragma unroll
        for (int i = 0; i < 4; i++) {
            int s = i * 256 + tid, row = s >> 3, c8 = s & 7;
            kreg[i] = *(const uint4*)(Kh + (long)(c*128 + row) * Ec + h * 64 + c8 * 8);
        }
        #pragma unroll
        for (int i = 0; i < 4; i++) {
            int s = i * 256 + tid, vr = s >> 4, c16 = s & 15;
            vreg[i] = *(const uint4*)(Vt + ((size_t)h * Dc + vr) * Mc + c*128 + c16 * 8);
        }
        __syncthreads();
        #pragma unroll
        for (int i = 0; i < 4; i++) {
            int s = i * 256 + tid, row = s >> 3, c8 = s & 7;
            *(uint4*)(sm + 16384 + SWZ((uint32_t)(row * 128 + c8 * 16))) = kreg[i];
        }
        #pragma unroll
        for (int i = 0; i < 4; i++) {
            int s = i * 256 + tid, vr = s >> 4, c16 = s & 15;
            *(uint4*)(sm + 32768 + (c16 >> 3) * 8192 +
                      SWZ((uint32_t)(vr * 128 + (c16 & 7) * 16))) = vreg[i];
        }
        __syncthreads();

        // scores S[16 x 128] per warp
        float acc_s[16][4];
        #pragma unroll
        for (int nt = 0; nt < 16; nt++)
            #pragma unroll
            for (int j = 0; j < 4; j++) acc_s[nt][j] = 0.f;
        #pragma unroll
        for (int ks = 0; ks < 4; ks++) {
            uint32_t kb = (uint32_t)ks * 32;
            uint32_t af[4];
            int arow = wid * 16 + ((t & 1) << 3) + r;
            ldm_x4(af, smQ + SWZ((uint32_t)(arow*128 + kb + ((t>>1)<<4))));
            uint32_t bf[32];
            #pragma unroll
            for (int p = 0; p < 8; p++) {
                int brow = p * 16 + ((t >> 1) << 3) + r;
                ldm_x4(&bf[p*4], smK + SWZ((uint32_t)(brow*128 + kb + ((t&1)<<4))));
            }
            #pragma unroll
            for (int nt = 0; nt < 16; nt++)
                mma_h(acc_s[nt], af, &bf[nt*2]);
        }

        // online softmax (row stats inside lane quads)
        #pragma unroll
        for (int sub = 0; sub < 2; sub++) {
            float mx = -1e30f;
            #pragma unroll
            for (int nt = 0; nt < 16; nt++)
                mx = fmaxf(mx, fmaxf(acc_s[nt][sub*2], acc_s[nt][sub*2+1]));
            mx = fmaxf(mx, __shfl_xor_sync(0xffffffffu, mx, 1));
            mx = fmaxf(mx, __shfl_xor_sync(0xffffffffu, mx, 2));
            float mn = fmaxf(m_run[sub], mx);
            float scl = __expf(m_run[sub] - mn);
            float sum = 0.f;
            #pragma unroll
            for (int nt = 0; nt < 16; nt++) {
                float p0 = __expf(acc_s[nt][sub*2]   - mn);
                float p1 = __expf(acc_s[nt][sub*2+1] - mn);
                acc_s[nt][sub*2] = p0; acc_s[nt][sub*2+1] = p1;
                sum += p0 + p1;
            }
            sum += __shfl_xor_sync(0xffffffffu, sum, 1);
            sum += __shfl_xor_sync(0xffffffffu, sum, 2);
            l_run[sub] = l_run[sub] * scl + sum;
            m_run[sub] = mn;
            #pragma unroll
            for (int nt = 0; nt < 8; nt++) {
                acc_o[nt][sub*2]   *= scl;
                acc_o[nt][sub*2+1] *= scl;
            }
        }

        // PV: O += P @ V^T (P fragments from registers)
        #pragma unroll
        for (int s = 0; s < 8; s++) {
            uint32_t ah[4];
            ah[0] = f2h2(acc_s[2*s][0],   acc_s[2*s][1]);
            ah[1] = f2h2(acc_s[2*s][2],   acc_s[2*s][3]);
            ah[2] = f2h2(acc_s[2*s+1][0], acc_s[2*s+1][1]);
            ah[3] = f2h2(acc_s[2*s+1][2], acc_s[2*s+1][3]);
            uint32_t vhalf = (uint32_t)(s >> 2) * 8192, kb2 = (uint32_t)(s & 3) * 32;
            uint32_t vf[16];
            #pragma unroll
            for (int p = 0; p < 4; p++) {
                int drow = p * 16 + ((t >> 1) << 3) + r;
                ldm_x4(&vf[p*4], smV + vhalf + SWZ((uint32_t)(drow*128 + kb2 + ((t&1)<<4))));
            }
            #pragma unroll
            for (int nt = 0; nt < 8; nt++)
                mma_h(acc_o[nt], ah, &vf[nt*2]);
        }
    }

    float inv0 = 1.f / l_run[0], inv1 = 1.f / l_run[1];
    long orow = (long)b * Sc + q0 + wid * 16 + (lane >> 2);
    __half* dst = O + orow * Ec + h * 64 + (lane & 3) * 2;
    #pragma unroll
    for (int nt = 0; nt < 8; nt++) {
        *(uint32_t*)(dst + nt*8) = f2h2(acc_o[nt][0] * inv0, acc_o[nt][1] * inv0);
        *(uint32_t*)(dst + 8*Ec + nt*8) = f2h2(acc_o[nt][2] * inv1, acc_o[nt][3] * inv1);
    }
}

// ---------------- V transpose: (M,E) fp16 -> per-head (D,M) fp16 -----------
__global__ void vtrans_kernel(const __half* __restrict__ V, __half* __restrict__ Vt)
{
    __shared__ __half tsh[32][33];
    int m0 = blockIdx.x * 32;
    int h  = blockIdx.y;
    int tx = threadIdx.x, ty = threadIdx.y;
    for (int d0 = 0; d0 < 64; d0 += 32) {
        for (int r2 = ty; r2 < 32; r2 += 8)
            tsh[r2][tx] = V[(long)(m0 + r2) * Ec + h * 64 + d0 + tx];
        __syncthreads();
        for (int r2 = ty; r2 < 32; r2 += 8)
            Vt[((size_t)h * Dc + d0 + r2) * Mc + m0 + tx] = tsh[tx][r2];
        __syncthreads();
    }
}

// ---------------- residual + LayerNorm -------------------------------------
__global__ void __launch_bounds__(256) resid_ln_kernel(
    const float* __restrict__ Pr, const float* __restrict__ Res,
    const float* __restrict__ gw, const float* __restrict__ bw,
    float* __restrict__ out)
{
    __shared__ float sA[8], sB[8];
    long row = blockIdx.x;
    int tt = threadIdx.x;
    long base = row * Ec + tt * 4;
    float4 p = *(const float4*)(Pr + base);
    float4 rv = *(const float4*)(Res + base);
    float v0 = p.x+rv.x, v1 = p.y+rv.y, v2 = p.z+rv.z, v3 = p.w+rv.w;
    float s  = v0+v1+v2+v3;
    float sq = v0*v0+v1*v1+v2*v2+v3*v3;
    int lane = tt & 31, wd = tt >> 5;
    #pragma unroll
    for (int o = 16; o; o >>= 1) {
        s  += __shfl_xor_sync(0xffffffffu, s,  o);
        sq += __shfl_xor_sync(0xffffffffu, sq, o);
    }
    if (lane == 0) { sA[wd] = s; sB[wd] = sq; }
    __syncthreads();
    if (tt < 32) {
        s  = (tt < 8) ? sA[tt] : 0.f;
        sq = (tt < 8) ? sB[tt] : 0.f;
        #pragma unroll
        for (int o = 4; o; o >>= 1) {
            s  += __shfl_xor_sync(0xffffffffu, s,  o);
            sq += __shfl_xor_sync(0xffffffffu, sq, o);
        }
        if (tt == 0) { sA[0] = s; sB[0] = sq; }
    }
    __syncthreads();
    float mu  = sA[0] * (1.f/Ec);
    float var = sB[0] * (1.f/Ec) - mu*mu;
    float rs  = rsqrtf(var + 1e-5f);
    float4 g4 = *(const float4*)(gw + tt*4);
    float4 b4 = *(const float4*)(bw + tt*4);
    float4 o4;
    o4.x = (v0-mu)*rs*g4.x + b4.x;
    o4.y = (v1-mu)*rs*g4.y + b4.y;
    o4.z = (v2-mu)*rs*g4.z + b4.z;
    o4.w = (v3-mu)*rs*g4.w + b4.w;
    *(float4*)(out + base) = o4;
}

// ---------------- gate + blend + LayerNorm ---------------------------------
__global__ void __launch_bounds__(256) newmem_ln_kernel(
    const float* __restrict__ gmem, const float* __restrict__ gupd,
    const float* __restrict__ updv, const float* __restrict__ mem,
    const float* __restrict__ gw, const float* __restrict__ bw,
    float* __restrict__ out)
{
    __shared__ float sA[8], sB[8];
    int rb = blockIdx.x;
    int b  = rb >> 9;
    int m  = rb & 511;
    int tt = threadIdx.x;
    int e  = tt * 4;
    float4 gm = *(const float4*)(gmem + (long)m*Ec + e);
    float4 gu = *(const float4*)(gupd + (long)b*Ec + e);
    float4 uu = *(const float4*)(updv + (long)b*Ec + e);
    float4 mm = *(const float4*)(mem  + (long)m*Ec + e);
    float g0 = 1.f/(1.f + __expf(-(gm.x + gu.x)));
    float g1 = 1.f/(1.f + __expf(-(gm.y + gu.y)));
    float g2 = 1.f/(1.f + __expf(-(gm.z + gu.z)));
    float g3 = 1.f/(1.f + __expf(-(gm.w + gu.w)));
    float v0 = g0*uu.x + (1.f-g0)*mm.x;
    float v1 = g1*uu.y + (1.f-g1)*mm.y;
    float v2 = g2*uu.z + (1.f-g2)*mm.z;
    float v3 = g3*uu.w + (1.f-g3)*mm.w;
    float s  = v0+v1+v2+v3;
    float sq = v0*v0+v1*v1+v2*v2+v3*v3;
    int lane = tt & 31, wd = tt >> 5;
    #pragma unroll
    for (int o = 16; o; o >>= 1) {
        s  += __shfl_xor_sync(0xffffffffu, s,  o);
        sq += __shfl_xor_sync(0xffffffffu, sq, o);
    }
    if (lane == 0) { sA[wd] = s; sB[wd] = sq; }
    __syncthreads();
    if (tt < 32) {
        s  = (tt < 8) ? sA[tt] : 0.f;
        sq = (tt < 8) ? sB[tt] : 0.f;
        #pragma unroll
        for (int o = 4; o; o >>= 1) {
            s  += __shfl_xor_sync(0xffffffffu, s,  o);
            sq += __shfl_xor_sync(0xffffffffu, sq, o);
        }
        if (tt == 0) { sA[0] = s; sB[0] = sq; }
    }
    __syncthreads();
    float mu  = sA[0] * (1.f/Ec);
    float var = sB[0] * (1.f/Ec) - mu*mu;
    float rs  = rsqrtf(var + 1e-5f);
    float4 g4 = *(const float4*)(gw + e);
    float4 b4 = *(const float4*)(bw + e);
    float4 o4;
    o4.x = (v0-mu)*rs*g4.x + b4.x;
    o4.y = (v1-mu)*rs*g4.y + b4.y;
    o4.z = (v2-mu)*rs*g4.z + b4.z;
    o4.w = (v3-mu)*rs*g4.w + b4.w;
    *(float4*)(out + (long)rb*Ec + e) = o4;
}

// ---------------- wq = mean over S ------------------------------------------
__global__ void __launch_bounds__(256) wq_partial_kernel(
    const float* __restrict__ Q, float* __restrict__ part)
{
    int e = blockIdx.x * 256 + threadIdx.x;
    int b = blockIdx.y;
    int z = blockIdx.z;
    const float* p = Q + ((long)b*Sc + (long)z*256) * Ec + e;
    float s = 0.f;
    for (int i = 0; i < 256; i++) s += p[(long)i * Ec];
    part[((long)z*Bc + b)*Ec + e] = s;
}
__global__ void __launch_bounds__(256) wq_final_kernel(
    const float* __restrict__ part, float* __restrict__ wq)
{
    int e = blockIdx.x * 256 + threadIdx.x;
    int b = blockIdx.y;
    float s = 0.f;
    #pragma unroll
    for (int z = 0; z < 8; z++) s += part[((long)z*Bc + b)*Ec + e];
    wq[(long)b*Ec + e] = s * (1.f/Sc);
}

// ---------------- per-batch GEMV -------------------------------------------
__global__ void __launch_bounds__(256) gemv_nt_kernel(
    const float* __restrict__ x, const float* __restrict__ W, long ldw,
    const float* __restrict__ bias, float* __restrict__ y)
{
    int j = blockIdx.x * 256 + threadIdx.x;
    int b = blockIdx.y;
    const float* wr = W + (long)j * ldw;
    const float* xb = x + (long)b * Ec;
    float acc = bias ? bias[j] : 0.f;
    for (int k = 0; k < Ec; k += 4) {
        float4 w4 = *(const float4*)(wr + k);
        float4 x4 = *(const float4*)(xb + k);
        acc += x4.x*w4.x + x4.y*w4.y + x4.z*w4.z + x4.w*w4.w;
    }
    y[(long)b*Ec + j] = acc;
}

// ---------------- host launcher --------------------------------------------
extern "C" void kernel_launch(void* const* d_in, const int* in_sizes, int n_in,
                              void* d_out, int out_size)
{
    const float* query   = (const float*)d_in[0];
    const float* memory  = (const float*)d_in[1];
    const float* r_in_w  = (const float*)d_in[2];
    const float* r_in_b  = (const float*)d_in[3];
    const float* r_out_w = (const float*)d_in[4];
    const float* r_out_b = (const float*)d_in[5];
    const float* w_in_w  = (const float*)d_in[6];
    const float* w_in_b  = (const float*)d_in[7];
    const float* w_out_w = (const float*)d_in[8];
    const float* w_out_b = (const float*)d_in[9];
    const float* rn_g    = (const float*)d_in[10];
    const float* rn_b    = (const float*)d_in[11];
    const float* wn_g    = (const float*)d_in[12];
    const float* wn_b    = (const float*)d_in[13];
    const float* gate_w  = (const float*)d_in[14];
    const float* gate_b  = (const float*)d_in[15];
    float* out = (float*)d_out;

    constexpr int SMEM_G = 65536;   // double-buffered 2 x (A 16K + B 16K)
    constexpr int SMEM_F = 49152;   // flash Q+K+V

    static float *pP = nullptr, *pG, *pWP, *pWQ, *pVW, *pUP, *pGU;
    static __half *pQh, *pAh, *pKh, *pVh, *pVt;
    if (!pP) {
        cudaGetSymbolAddress((void**)&pG,   g_gmem);
        cudaGetSymbolAddress((void**)&pQh,  g_Qh);
        cudaGetSymbolAddress((void**)&pAh,  g_Ah);
        cudaGetSymbolAddress((void**)&pKh,  g_Kh);
        cudaGetSymbolAddress((void**)&pVh,  g_Vh);
        cudaGetSymbolAddress((void**)&pVt,  g_Vt);
        cudaGetSymbolAddress((void**)&pWP,  g_wqpart);
        cudaGetSymbolAddress((void**)&pWQ,  g_wq);
        cudaGetSymbolAddress((void**)&pVW,  g_vw);
        cudaGetSymbolAddress((void**)&pUP,  g_upd);
        cudaGetSymbolAddress((void**)&pGU,  g_gupd);
        cudaFuncSetAttribute(proj4_kernel,
            cudaFuncAttributeMaxDynamicSharedMemorySize, SMEM_G);
        cudaFuncSetAttribute(hgemm16_kernel,
            cudaFuncAttributeMaxDynamicSharedMemorySize, SMEM_G);
        cudaFuncSetAttribute(flash_kernel,
            cudaFuncAttributeMaxDynamicSharedMemorySize, SMEM_F);
        cudaGetSymbolAddress((void**)&pP,   g_proj);   // last: guards init
    }

    // projections (Q/K/V/gate in one launch; Q pre-scaled by 1/8, fp16 out)
    proj4_kernel<<<dim3(8,140), 256, SMEM_G>>>(
        query, memory, r_in_w, r_in_b, gate_w, gate_b, pQh, pKh, pVh, pG);

    // attention
    vtrans_kernel<<<dim3(Mc/32, Hc), dim3(32,8)>>>(pVh, pVt);
    flash_kernel<<<dim3(Sc/128, ZNc), 256, SMEM_F>>>(pQh, pKh, pVt, pAh);

    // out-proj + residual LN -> mem_out
    hgemm16_kernel<<<dim3(8,128), 256, SMEM_G>>>(pAh, r_out_w, r_out_b, pP,
                                                 Ec, Ec, Ec, Ec);
    resid_ln_kernel<<<Bc*Sc, 256>>>(pP, query, rn_g, rn_b, out);

    // write path (softmax over length-1 keys == 1)
    wq_partial_kernel<<<dim3(Ec/256, Bc, 8), 256>>>(query, pWP);
    wq_final_kernel  <<<dim3(Ec/256, Bc),    256>>>(pWP, pWQ);
    gemv_nt_kernel<<<dim3(Ec/256, Bc), 256>>>(pWQ, w_in_w + (size_t)2*Ec*Ec, Ec,   w_in_b + 2*Ec, pVW);
    gemv_nt_kernel<<<dim3(Ec/256, Bc), 256>>>(pVW, w_out_w,                  Ec,   w_out_b,       pUP);
    gemv_nt_kernel<<<dim3(Ec/256, Bc), 256>>>(pUP, gate_w + Ec,              2*Ec, nullptr,       pGU);
    newmem_ln_kernel<<<Bc*Mc, 256>>>(pG, pGU, pUP, memory, wn_g, wn_b,
                                     out + (size_t)Bc*Sc*Ec);
}